// round 1
// baseline (speedup 1.0000x reference)
#include <cuda_runtime.h>
#include <math.h>

#define NN 20000
#define EE 180000
#define DD 768
#define SS 512
#define BS 8192      // B*S
#define HH 128       // HEADS*HID

// ---------------- scratch (device globals; no runtime alloc) ----------------
__device__ float g_hs1[NN * HH];
__device__ float g_hd1[NN * HH];
__device__ float g_h1 [NN * HH];
__device__ float g_hs2[NN * DD];
__device__ float g_hd2[NN * DD];
__device__ float g_emb[NN * DD];
__device__ float g_pe [SS * DD];
__device__ int   g_deg[NN];
__device__ int   g_off[NN];
__device__ int   g_cur[NN];
__device__ int   g_flag[NN];
__device__ int   g_list[NN];
__device__ int   g_srcs[EE];
__device__ int   g_cnt;

__device__ __forceinline__ float lrelu(float x) { return x > 0.f ? x : 0.2f * x; }
__device__ __forceinline__ float elu1(float x)  { return x > 0.f ? x : expm1f(x); }

// ---------------- init: zero counters ----------------
__global__ void k_init() {
    int i = blockIdx.x * blockDim.x + threadIdx.x;
    int stride = gridDim.x * blockDim.x;
    for (int j = i; j < NN; j += stride) { g_deg[j] = 0; g_cur[j] = 0; g_flag[j] = 0; }
    if (i == 0) g_cnt = 0;
}

// ---------------- layer-1 input projections: hs1/hd1 = feature @ W ----------------
__global__ void k_gemm1(const float* __restrict__ feat,
                        const float* __restrict__ Ws, const float* __restrict__ Wd) {
    __shared__ float ws[4 * HH], wd[4 * HH];
    int t = threadIdx.x;                     // 128
    for (int i = t; i < 4 * HH; i += 128) { ws[i] = Ws[i]; wd[i] = Wd[i]; }
    __syncthreads();
    int n0 = blockIdx.x * 16;
    int n1 = min(NN, n0 + 16);
    for (int n = n0; n < n1; n++) {
        float f0 = feat[n * 4 + 0], f1 = feat[n * 4 + 1], f2 = feat[n * 4 + 2], f3 = feat[n * 4 + 3];
        float s = f0 * ws[t] + f1 * ws[HH + t] + f2 * ws[2 * HH + t] + f3 * ws[3 * HH + t];
        float d = f0 * wd[t] + f1 * wd[HH + t] + f2 * wd[2 * HH + t] + f3 * wd[3 * HH + t];
        g_hs1[n * HH + t] = s;
        g_hd1[n * HH + t] = d;
    }
}

// ---------------- CSR build ----------------
__global__ void k_hist(const int* __restrict__ dst) {
    int i = blockIdx.x * blockDim.x + threadIdx.x;
    int stride = gridDim.x * blockDim.x;
    for (int e = i; e < EE; e += stride) atomicAdd(&g_deg[dst[e]], 1);
}

__global__ void k_flag(const int* __restrict__ trj) {
    int i = blockIdx.x * blockDim.x + threadIdx.x;
    int stride = gridDim.x * blockDim.x;
    for (int j = i; j < BS; j += stride) {
        int tok = trj[j];
        if (atomicExch(&g_flag[tok], 1) == 0) {
            int p = atomicAdd(&g_cnt, 1);
            g_list[p] = tok;
        }
    }
}

__global__ void k_scan() {      // single block, 1024 threads: exclusive scan of g_deg -> g_off
    __shared__ int sh[1024];
    int t = threadIdx.x;
    int carry = 0;
    for (int base = 0; base < NN; base += 1024) {
        int i = base + t;
        int v = (i < NN) ? g_deg[i] : 0;
        sh[t] = v;
        __syncthreads();
        for (int off = 1; off < 1024; off <<= 1) {
            int add = (t >= off) ? sh[t - off] : 0;
            __syncthreads();
            sh[t] += add;
            __syncthreads();
        }
        if (i < NN) g_off[i] = carry + sh[t] - v;
        carry += sh[1023];
        __syncthreads();
    }
}

__global__ void k_scatter(const int* __restrict__ src, const int* __restrict__ dst) {
    int i = blockIdx.x * blockDim.x + threadIdx.x;
    int stride = gridDim.x * blockDim.x;
    for (int e = i; e < EE; e += stride) {
        int d = dst[e];
        int pos = g_off[d] + atomicAdd(&g_cur[d], 1);
        g_srcs[pos] = src[e];
    }
}

// ---------------- layer-1: warp per node, online softmax over in-edges ----------------
__global__ void k_layer1(const float* __restrict__ attn1) {
    int v = (blockIdx.x << 3) + (threadIdx.x >> 5);
    if (v >= NN) return;
    int lane = threadIdx.x & 31;
    int jb = lane * 4;                      // lane owns features j = 4l..4l+3 (head = l>>2)

    float4 hd = *(const float4*)&g_hd1[v * HH + jb];
    float4 at = *(const float4*)&attn1[jb];
    float4 acc = make_float4(0.f, 0.f, 0.f, 0.f);
    float m = -INFINITY, den = 0.f;

    int st = g_off[v], dg = g_deg[v];
    for (int e = 0; e < dg; e++) {
        int u = g_srcs[st + e];
        float4 hs = *(const float4*)&g_hs1[u * HH + jb];
        float s = lrelu(hs.x + hd.x) * at.x + lrelu(hs.y + hd.y) * at.y
                + lrelu(hs.z + hd.z) * at.z + lrelu(hs.w + hd.w) * at.w;
        s += __shfl_xor_sync(0xffffffffu, s, 1);
        s += __shfl_xor_sync(0xffffffffu, s, 2);   // per-head (4-lane group) score
        float nm = fmaxf(m, s);
        float c = __expf(m - nm);
        float p = __expf(s - nm);
        den = den * c + p;
        acc.x = acc.x * c + p * hs.x;
        acc.y = acc.y * c + p * hs.y;
        acc.z = acc.z * c + p * hs.z;
        acc.w = acc.w * c + p * hs.w;
        m = nm;
    }
    float inv = 1.f / den;
    float* o = &g_h1[v * HH + jb];
    o[0] = elu1(acc.x * inv);
    o[1] = elu1(acc.y * inv);
    o[2] = elu1(acc.z * inv);
    o[3] = elu1(acc.w * inv);
}

// ---------------- layer-2 GEMM: C = h1 @ W  (64x64 tile, K=128) ----------------
// use_list=0: all NN rows -> g_hs2 ; use_list=1: g_cnt rows via g_list -> g_hd2
__global__ void k_gemm2(const float* __restrict__ W, int use_list) {
    int M_eff = use_list ? g_cnt : NN;
    int bm = blockIdx.y, bn = blockIdx.x;
    if (bm * 64 >= M_eff) return;

    __shared__ float Ast[32][64];   // [k][m] transposed chunk
    __shared__ float Bs [32][64];   // [k][n]

    int tid = threadIdx.x;          // 256
    int tx = tid & 15, ty = tid >> 4;
    float acc[4][4];
#pragma unroll
    for (int i = 0; i < 4; i++)
#pragma unroll
        for (int j = 0; j < 4; j++) acc[i][j] = 0.f;

    int lm  = tid >> 3;             // 0..31 (A row within half-tile)
    int lkq = tid & 7;              // 0..7  (A k-quad)
    int gr0 = bm * 64 + lm;
    int gr1 = gr0 + 32;
    bool v0 = gr0 < M_eff, v1 = gr1 < M_eff;
    int r0 = v0 ? (use_list ? g_list[gr0] : gr0) : 0;
    int r1 = v1 ? (use_list ? g_list[gr1] : gr1) : 0;

    int bk  = tid >> 4;             // 0..15 (B row)
    int bn4 = (tid & 15) * 4;

    for (int k0 = 0; k0 < HH; k0 += 32) {
        __syncthreads();
        float4 a0 = v0 ? *(const float4*)&g_h1[r0 * HH + k0 + lkq * 4] : make_float4(0, 0, 0, 0);
        float4 a1 = v1 ? *(const float4*)&g_h1[r1 * HH + k0 + lkq * 4] : make_float4(0, 0, 0, 0);
        Ast[lkq * 4 + 0][lm] = a0.x; Ast[lkq * 4 + 1][lm] = a0.y;
        Ast[lkq * 4 + 2][lm] = a0.z; Ast[lkq * 4 + 3][lm] = a0.w;
        Ast[lkq * 4 + 0][lm + 32] = a1.x; Ast[lkq * 4 + 1][lm + 32] = a1.y;
        Ast[lkq * 4 + 2][lm + 32] = a1.z; Ast[lkq * 4 + 3][lm + 32] = a1.w;
        float4 b0 = *(const float4*)&W[(k0 + bk) * DD + bn * 64 + bn4];
        float4 b1 = *(const float4*)&W[(k0 + bk + 16) * DD + bn * 64 + bn4];
        *(float4*)&Bs[bk][bn4] = b0;
        *(float4*)&Bs[bk + 16][bn4] = b1;
        __syncthreads();
#pragma unroll
        for (int k = 0; k < 32; k++) {
            float4 a = *(const float4*)&Ast[k][ty * 4];
            float4 b = *(const float4*)&Bs[k][tx * 4];
            acc[0][0] += a.x * b.x; acc[0][1] += a.x * b.y; acc[0][2] += a.x * b.z; acc[0][3] += a.x * b.w;
            acc[1][0] += a.y * b.x; acc[1][1] += a.y * b.y; acc[1][2] += a.y * b.z; acc[1][3] += a.y * b.w;
            acc[2][0] += a.z * b.x; acc[2][1] += a.z * b.y; acc[2][2] += a.z * b.z; acc[2][3] += a.z * b.w;
            acc[3][0] += a.w * b.x; acc[3][1] += a.w * b.y; acc[3][2] += a.w * b.z; acc[3][3] += a.w * b.w;
        }
    }
    float* C = use_list ? g_hd2 : g_hs2;
#pragma unroll
    for (int i = 0; i < 4; i++) {
        int gr = bm * 64 + ty * 4 + i;
        if (gr < M_eff) {
            int rr = use_list ? g_list[gr] : gr;
            float4 o = make_float4(acc[i][0], acc[i][1], acc[i][2], acc[i][3]);
            *(float4*)&C[rr * DD + bn * 64 + tx * 4] = o;
        }
    }
}

// ---------------- layer-2: warp per (needed) node, online softmax ----------------
__global__ void k_layer2(const float* __restrict__ attn2) {
    __shared__ float at_sh[DD];
    for (int i = threadIdx.x; i < DD; i += 256) at_sh[i] = attn2[i];
    __syncthreads();

    int v = (blockIdx.x << 3) + (threadIdx.x >> 5);
    if (v >= NN || !g_flag[v]) return;
    int lane = threadIdx.x & 31;
    int jb = lane * 4;

    float4 hd[6], acc[6];
#pragma unroll
    for (int i = 0; i < 6; i++) {
        hd[i] = *(const float4*)&g_hd2[v * DD + i * 128 + jb];
        acc[i] = make_float4(0.f, 0.f, 0.f, 0.f);
    }
    float m = -INFINITY, den = 0.f;

    int st = g_off[v], dg = g_deg[v];
    for (int e = 0; e < dg; e++) {
        int u = g_srcs[st + e];
        const float* hrow = &g_hs2[u * DD];
        float4 hs[6];
        float s = 0.f;
#pragma unroll
        for (int i = 0; i < 6; i++) {
            hs[i] = *(const float4*)&hrow[i * 128 + jb];
            float4 a = *(const float4*)&at_sh[i * 128 + jb];
            s += lrelu(hs[i].x + hd[i].x) * a.x + lrelu(hs[i].y + hd[i].y) * a.y
               + lrelu(hs[i].z + hd[i].z) * a.z + lrelu(hs[i].w + hd[i].w) * a.w;
        }
#pragma unroll
        for (int o = 16; o; o >>= 1) s += __shfl_xor_sync(0xffffffffu, s, o);
        float nm = fmaxf(m, s);
        float c = __expf(m - nm);
        float p = __expf(s - nm);
        den = den * c + p;
#pragma unroll
        for (int i = 0; i < 6; i++) {
            acc[i].x = acc[i].x * c + p * hs[i].x;
            acc[i].y = acc[i].y * c + p * hs[i].y;
            acc[i].z = acc[i].z * c + p * hs[i].z;
            acc[i].w = acc[i].w * c + p * hs[i].w;
        }
        m = nm;
    }
    float inv = 1.f / den;
#pragma unroll
    for (int i = 0; i < 6; i++) {
        float4 o = make_float4(acc[i].x * inv, acc[i].y * inv, acc[i].z * inv, acc[i].w * inv);
        *(float4*)&g_emb[v * DD + i * 128 + jb] = o;
    }
}

// ---------------- positional embedding table ----------------
__global__ void k_pe() {
    int idx = blockIdx.x * blockDim.x + threadIdx.x;
    if (idx >= SS * DD) return;
    int s = idx / DD, d = idx % DD;
    int i2 = d >> 1;
    float div = __expf((float)(2 * i2) * (-9.210340371976184f / (float)DD));
    float ang = (float)s * div;
    g_pe[idx] = (d & 1) ? cosf(ang) : sinf(ang);
}

// ---------------- final gather + sum ----------------
__global__ void k_out(const int* __restrict__ trj, const int* __restrict__ mins,
                      const int* __restrict__ wkd, const int* __restrict__ day,
                      const int* __restrict__ grd,
                      const float* __restrict__ grid_tab, const float* __restrict__ dayt_tab,
                      const float* __restrict__ wk_tab, const float* __restrict__ day_tab,
                      float* __restrict__ out) {
    int r = blockIdx.x;                 // 0..BS-1
    int tok = trj[r], mn = mins[r], wk = wkd[r], dy = day[r], gd = grd[r];
    int s = r & (SS - 1);
    int j = threadIdx.x * 4;            // 192 threads * 4 = 768
    float4 a = *(const float4*)&g_pe[s * DD + j];
    float4 b = *(const float4*)&g_emb[tok * DD + j];
    float4 c = *(const float4*)&wk_tab[wk * DD + j];
    float4 d = *(const float4*)&dayt_tab[mn * DD + j];
    float4 e = *(const float4*)&day_tab[dy * DD + j];
    float4 f = *(const float4*)&grid_tab[gd * DD + j];
    float4 o;
    o.x = a.x + b.x + c.x + d.x + e.x + f.x;
    o.y = a.y + b.y + c.y + d.y + e.y + f.y;
    o.z = a.z + b.z + c.z + d.z + e.z + f.z;
    o.w = a.w + b.w + c.w + d.w + e.w + f.w;
    *(float4*)&out[r * DD + j] = o;
}

// ---------------- launch ----------------
extern "C" void kernel_launch(void* const* d_in, const int* in_sizes, int n_in,
                              void* d_out, int out_size) {
    const int*   trj      = (const int*)d_in[0];
    const int*   min_list = (const int*)d_in[1];
    const int*   wkd_list = (const int*)d_in[2];
    const int*   day_list = (const int*)d_in[3];
    const int*   grd_list = (const int*)d_in[4];
    // d_in[5] = poi_list (unused)
    const int*   e_src    = (const int*)d_in[6];
    const int*   e_dst    = (const int*)d_in[7];
    const float* feat     = (const float*)d_in[8];
    const float* W_src1   = (const float*)d_in[9];
    const float* W_dst1   = (const float*)d_in[10];
    const float* attn1    = (const float*)d_in[11];
    const float* W_src2   = (const float*)d_in[12];
    const float* W_dst2   = (const float*)d_in[13];
    const float* attn2    = (const float*)d_in[14];
    const float* grid_tab = (const float*)d_in[15];
    const float* dayt_tab = (const float*)d_in[16];
    const float* wk_tab   = (const float*)d_in[17];
    const float* day_tab  = (const float*)d_in[18];
    float* out = (float*)d_out;

    k_init<<<80, 256>>>();
    k_pe<<<(SS * DD + 255) / 256, 256>>>();
    k_gemm1<<<(NN + 15) / 16, 128>>>(feat, W_src1, W_dst1);
    k_hist<<<352, 512>>>(e_dst);
    k_flag<<<32, 256>>>(trj);
    k_scan<<<1, 1024>>>();
    k_scatter<<<352, 512>>>(e_src, e_dst);
    k_layer1<<<(NN + 7) / 8, 256>>>(attn1);
    dim3 g2(DD / 64, (NN + 63) / 64);
    k_gemm2<<<g2, 256>>>(W_src2, 0);   // hs2: all nodes
    k_gemm2<<<g2, 256>>>(W_dst2, 1);   // hd2: only needed (flagged) nodes
    k_layer2<<<(NN + 7) / 8, 256>>>(attn2);
    k_out<<<BS, 192>>>(trj, min_list, wkd_list, day_list, grd_list,
                       grid_tab, dayt_tab, wk_tab, day_tab, out);
}

// round 3
// speedup vs baseline: 1.3424x; 1.3424x over previous
#include <cuda_runtime.h>
#include <cuda_bf16.h>
#include <math.h>
#include <stdint.h>

#define NN 20000
#define EE 180000
#define DD 768
#define SS 512
#define BS 8192      // B*S
#define HH 128       // HEADS*HID
#define STRD 136     // padded SMEM row stride (bf16 elems)

// ---------------- scratch (device globals; no runtime alloc) ----------------
__device__ float g_hs1[NN * HH];
__device__ float g_hd1[NN * HH];
__device__ __nv_bfloat16 g_h1h[NN * HH];
__device__ __nv_bfloat16 g_h1l[NN * HH];
__device__ __nv_bfloat16 g_wsh[DD * HH];
__device__ __nv_bfloat16 g_wsl[DD * HH];
__device__ __nv_bfloat16 g_wdh[DD * HH];
__device__ __nv_bfloat16 g_wdl[DD * HH];
__device__ float g_hs2[NN * DD];
__device__ float g_hd2[NN * DD];
__device__ float g_emb[NN * DD];
__device__ float g_pe [SS * DD];
__device__ int   g_deg[NN];
__device__ int   g_off[NN];
__device__ int   g_cur[NN];
__device__ int   g_flag[NN];
__device__ int   g_list[NN];
__device__ int   g_srcs[EE];
__device__ int   g_cnt;

__device__ __forceinline__ float lrelu(float x) { return x > 0.f ? x : 0.2f * x; }
__device__ __forceinline__ float elu1(float x)  { return x > 0.f ? x : expm1f(x); }

__device__ __forceinline__ uint32_t smem_u32(const void* p) {
    uint32_t a;
    asm("{ .reg .u64 t; cvta.to.shared.u64 t, %1; cvt.u32.u64 %0, t; }" : "=r"(a) : "l"(p));
    return a;
}

#define LDSM_X4(r0, r1, r2, r3, addr) \
    asm volatile("ldmatrix.sync.aligned.m8n8.x4.shared.b16 {%0,%1,%2,%3}, [%4];" \
                 : "=r"(r0), "=r"(r1), "=r"(r2), "=r"(r3) : "r"(addr))

#define MMA16816(c, a0, a1, a2, a3, b0, b1) \
    asm volatile("mma.sync.aligned.m16n8k16.row.col.f32.bf16.bf16.f32 " \
                 "{%0,%1,%2,%3}, {%4,%5,%6,%7}, {%8,%9}, {%0,%1,%2,%3};" \
                 : "+f"((c)[0]), "+f"((c)[1]), "+f"((c)[2]), "+f"((c)[3]) \
                 : "r"(a0), "r"(a1), "r"(a2), "r"(a3), "r"(b0), "r"(b1))

// ---------------- init ----------------
__global__ void k_init() {
    int i = blockIdx.x * blockDim.x + threadIdx.x;
    int stride = gridDim.x * blockDim.x;
    for (int j = i; j < NN; j += stride) { g_deg[j] = 0; g_cur[j] = 0; g_flag[j] = 0; }
    if (i == 0) g_cnt = 0;
}

// ---------------- layer-1 input projections ----------------
__global__ void k_gemm1(const float* __restrict__ feat,
                        const float* __restrict__ Ws, const float* __restrict__ Wd) {
    __shared__ float ws[4 * HH], wd[4 * HH];
    int t = threadIdx.x;                     // 128
    for (int i = t; i < 4 * HH; i += 128) { ws[i] = Ws[i]; wd[i] = Wd[i]; }
    __syncthreads();
    int n0 = blockIdx.x * 16;
    int n1 = min(NN, n0 + 16);
    for (int n = n0; n < n1; n++) {
        float f0 = feat[n * 4 + 0], f1 = feat[n * 4 + 1], f2 = feat[n * 4 + 2], f3 = feat[n * 4 + 3];
        float s = f0 * ws[t] + f1 * ws[HH + t] + f2 * ws[2 * HH + t] + f3 * ws[3 * HH + t];
        float d = f0 * wd[t] + f1 * wd[HH + t] + f2 * wd[2 * HH + t] + f3 * wd[3 * HH + t];
        g_hs1[n * HH + t] = s;
        g_hd1[n * HH + t] = d;
    }
}

// ---------------- CSR build ----------------
__global__ void k_hist(const int* __restrict__ dst) {
    int i = blockIdx.x * blockDim.x + threadIdx.x;
    int stride = gridDim.x * blockDim.x;
    for (int e = i; e < EE; e += stride) atomicAdd(&g_deg[dst[e]], 1);
}

__global__ void k_flag(const int* __restrict__ trj) {
    int i = blockIdx.x * blockDim.x + threadIdx.x;
    int stride = gridDim.x * blockDim.x;
    for (int j = i; j < BS; j += stride) {
        int tok = trj[j];
        if (atomicExch(&g_flag[tok], 1) == 0) {
            int p = atomicAdd(&g_cnt, 1);
            g_list[p] = tok;
        }
    }
}

__global__ void k_scan() {
    __shared__ int sh[1024];
    int t = threadIdx.x;
    int carry = 0;
    for (int base = 0; base < NN; base += 1024) {
        int i = base + t;
        int v = (i < NN) ? g_deg[i] : 0;
        sh[t] = v;
        __syncthreads();
        for (int off = 1; off < 1024; off <<= 1) {
            int add = (t >= off) ? sh[t - off] : 0;
            __syncthreads();
            sh[t] += add;
            __syncthreads();
        }
        if (i < NN) g_off[i] = carry + sh[t] - v;
        carry += sh[1023];
        __syncthreads();
    }
}

__global__ void k_scatter(const int* __restrict__ src, const int* __restrict__ dst) {
    int i = blockIdx.x * blockDim.x + threadIdx.x;
    int stride = gridDim.x * blockDim.x;
    for (int e = i; e < EE; e += stride) {
        int d = dst[e];
        int pos = g_off[d] + atomicAdd(&g_cur[d], 1);
        g_srcs[pos] = src[e];
    }
}

// ---------------- layer-1: warp per node, online softmax; emit bf16 hi/lo ----------------
__global__ void k_layer1(const float* __restrict__ attn1) {
    int v = (blockIdx.x << 3) + (threadIdx.x >> 5);
    if (v >= NN) return;
    int lane = threadIdx.x & 31;
    int jb = lane * 4;

    float4 hd = *(const float4*)&g_hd1[v * HH + jb];
    float4 at = *(const float4*)&attn1[jb];
    float4 acc = make_float4(0.f, 0.f, 0.f, 0.f);
    float m = -INFINITY, den = 0.f;

    int st = g_off[v], dg = g_deg[v];
    for (int e = 0; e < dg; e++) {
        int u = g_srcs[st + e];
        float4 hs = *(const float4*)&g_hs1[u * HH + jb];
        float s = lrelu(hs.x + hd.x) * at.x + lrelu(hs.y + hd.y) * at.y
                + lrelu(hs.z + hd.z) * at.z + lrelu(hs.w + hd.w) * at.w;
        s += __shfl_xor_sync(0xffffffffu, s, 1);
        s += __shfl_xor_sync(0xffffffffu, s, 2);
        float nm = fmaxf(m, s);
        float c = __expf(m - nm);
        float p = __expf(s - nm);
        den = den * c + p;
        acc.x = acc.x * c + p * hs.x;
        acc.y = acc.y * c + p * hs.y;
        acc.z = acc.z * c + p * hs.z;
        acc.w = acc.w * c + p * hs.w;
        m = nm;
    }
    float inv = 1.f / den;
    float o[4];
    o[0] = elu1(acc.x * inv); o[1] = elu1(acc.y * inv);
    o[2] = elu1(acc.z * inv); o[3] = elu1(acc.w * inv);
#pragma unroll
    for (int i = 0; i < 4; i++) {
        __nv_bfloat16 h = __float2bfloat16(o[i]);
        g_h1h[v * HH + jb + i] = h;
        g_h1l[v * HH + jb + i] = __float2bfloat16(o[i] - __bfloat162float(h));
    }
}

// ---------------- W2 transpose + bf16 split ----------------
__global__ void k_wsplit(const float* __restrict__ Ws, const float* __restrict__ Wd) {
    int i = blockIdx.x * blockDim.x + threadIdx.x;
    if (i >= DD * HH) return;
    int n = i >> 7, k = i & 127;
    float ws = Ws[k * DD + n];
    __nv_bfloat16 h = __float2bfloat16(ws);
    g_wsh[i] = h;
    g_wsl[i] = __float2bfloat16(ws - __bfloat162float(h));
    float wd = Wd[k * DD + n];
    h = __float2bfloat16(wd);
    g_wdh[i] = h;
    g_wdl[i] = __float2bfloat16(wd - __bfloat162float(h));
}

// ---------------- layer-2 GEMM via mma.sync bf16x3: C = h1 @ W ----------------
// A: g_h1h/g_h1l [M][128] bf16 ; B: W planes [768][128] bf16 (k contiguous)
// CTA tile 128x128, K=128 resident. 8 warps as 4(m) x 2(n); warp tile 32x64.
__global__ void __launch_bounds__(256, 1) k_gemm2_mma(
        const __nv_bfloat16* __restrict__ Bh, const __nv_bfloat16* __restrict__ Bl,
        float* __restrict__ C, int use_list) {
    extern __shared__ __nv_bfloat16 sm[];
    __nv_bfloat16* Ah_s = sm;
    __nv_bfloat16* Al_s = sm + 128 * STRD;
    __nv_bfloat16* Bh_s = sm + 2 * 128 * STRD;
    __nv_bfloat16* Bl_s = sm + 3 * 128 * STRD;

    const int M_eff = use_list ? g_cnt : NN;
    const int bm = blockIdx.y, bn = blockIdx.x;
    if (bm * 128 >= M_eff) return;
    const int row0 = bm * 128, n0 = bn * 128;
    const int tid = threadIdx.x;

    // global -> SMEM (padded rows)
    const uint4 z4 = make_uint4(0, 0, 0, 0);
    for (int i = tid; i < 2048; i += 256) {
        int r = i >> 4, ck = i & 15;
        int so = r * STRD + ck * 8;
        int gr = row0 + r;
        uint4 vh = z4, vl = z4;
        if (gr < M_eff) {
            int rr = use_list ? g_list[gr] : gr;
            vh = *(const uint4*)&g_h1h[rr * HH + ck * 8];
            vl = *(const uint4*)&g_h1l[rr * HH + ck * 8];
        }
        *(uint4*)&Ah_s[so] = vh;
        *(uint4*)&Al_s[so] = vl;
        int gn = n0 + r;
        *(uint4*)&Bh_s[so] = *(const uint4*)&Bh[gn * HH + ck * 8];
        *(uint4*)&Bl_s[so] = *(const uint4*)&Bl[gn * HH + ck * 8];
    }
    __syncthreads();

    const int wid = tid >> 5, lane = tid & 31;
    const int wm = (wid >> 1) * 32, wn = (wid & 1) * 64;

    float acc[2][8][4];
#pragma unroll
    for (int mt = 0; mt < 2; mt++)
#pragma unroll
        for (int nt = 0; nt < 8; nt++)
#pragma unroll
            for (int c = 0; c < 4; c++) acc[mt][nt][c] = 0.f;

    // ldmatrix source addresses (element offsets; *2 for bytes)
    // A: row = wm + mt*16 + (lane&15), kcol = ks*16 + (lane>>4)*8
    const int a_row = wm + (lane & 15);
    const int a_kof = (lane >> 4) * 8;
    // B x4 covering 2 n-octets: q = lane>>3: 0:(n+rrow,k+0) 1:(n+rrow,k+8) 2:(n+8+rrow,k+0) 3:(n+8+rrow,k+8)
    const int q = lane >> 3, rrow = lane & 7;
    const int b_nof = ((q >> 1) ? 8 : 0) + rrow;
    const int b_kof = (q & 1) * 8;

    const uint32_t sAh = smem_u32(Ah_s), sAl = smem_u32(Al_s);
    const uint32_t sBh = smem_u32(Bh_s), sBl = smem_u32(Bl_s);

#pragma unroll
    for (int ks = 0; ks < 8; ks++) {
        const int kbase = ks * 16;
        uint32_t ah[2][4], al[2][4], bh[8][2], bl[8][2];
#pragma unroll
        for (int mt = 0; mt < 2; mt++) {
            uint32_t ad = sAh + ((a_row + mt * 16) * STRD + kbase + a_kof) * 2;
            LDSM_X4(ah[mt][0], ah[mt][1], ah[mt][2], ah[mt][3], ad);
        }
#pragma unroll
        for (int np = 0; np < 4; np++) {
            uint32_t bd = sBh + ((wn + np * 16 + b_nof) * STRD + kbase + b_kof) * 2;
            LDSM_X4(bh[np * 2][0], bh[np * 2][1], bh[np * 2 + 1][0], bh[np * 2 + 1][1], bd);
        }
#pragma unroll
        for (int mt = 0; mt < 2; mt++)
#pragma unroll
            for (int nt = 0; nt < 8; nt++)
                MMA16816(acc[mt][nt], ah[mt][0], ah[mt][1], ah[mt][2], ah[mt][3],
                         bh[nt][0], bh[nt][1]);
#pragma unroll
        for (int mt = 0; mt < 2; mt++) {
            uint32_t ad = sAl + ((a_row + mt * 16) * STRD + kbase + a_kof) * 2;
            LDSM_X4(al[mt][0], al[mt][1], al[mt][2], al[mt][3], ad);
        }
#pragma unroll
        for (int mt = 0; mt < 2; mt++)
#pragma unroll
            for (int nt = 0; nt < 8; nt++)
                MMA16816(acc[mt][nt], al[mt][0], al[mt][1], al[mt][2], al[mt][3],
                         bh[nt][0], bh[nt][1]);
#pragma unroll
        for (int np = 0; np < 4; np++) {
            uint32_t bd = sBl + ((wn + np * 16 + b_nof) * STRD + kbase + b_kof) * 2;
            LDSM_X4(bl[np * 2][0], bl[np * 2][1], bl[np * 2 + 1][0], bl[np * 2 + 1][1], bd);
        }
#pragma unroll
        for (int mt = 0; mt < 2; mt++)
#pragma unroll
            for (int nt = 0; nt < 8; nt++)
                MMA16816(acc[mt][nt], ah[mt][0], ah[mt][1], ah[mt][2], ah[mt][3],
                         bl[nt][0], bl[nt][1]);
    }

    // epilogue
    const int gid = lane >> 2, tig = lane & 3;
#pragma unroll
    for (int mt = 0; mt < 2; mt++) {
        int grow0 = row0 + wm + mt * 16 + gid;
        int grow1 = grow0 + 8;
        bool v0 = grow0 < M_eff, v1 = grow1 < M_eff;
        int rr0 = v0 ? (use_list ? g_list[grow0] : grow0) : 0;
        int rr1 = v1 ? (use_list ? g_list[grow1] : grow1) : 0;
#pragma unroll
        for (int nt = 0; nt < 8; nt++) {
            int col = n0 + wn + nt * 8 + tig * 2;
            if (v0) *(float2*)&C[(size_t)rr0 * DD + col] = make_float2(acc[mt][nt][0], acc[mt][nt][1]);
            if (v1) *(float2*)&C[(size_t)rr1 * DD + col] = make_float2(acc[mt][nt][2], acc[mt][nt][3]);
        }
    }
}

// ---------------- layer-2: warp per flagged node, online softmax ----------------
__global__ void k_layer2(const float* __restrict__ attn2) {
    __shared__ float at_sh[DD];
    for (int i = threadIdx.x; i < DD; i += 256) at_sh[i] = attn2[i];
    __syncthreads();

    int v = (blockIdx.x << 3) + (threadIdx.x >> 5);
    if (v >= NN || !g_flag[v]) return;
    int lane = threadIdx.x & 31;
    int jb = lane * 4;

    float4 hd[6], acc[6];
#pragma unroll
    for (int i = 0; i < 6; i++) {
        hd[i] = *(const float4*)&g_hd2[v * DD + i * 128 + jb];
        acc[i] = make_float4(0.f, 0.f, 0.f, 0.f);
    }
    float m = -INFINITY, den = 0.f;

    int st = g_off[v], dg = g_deg[v];
    for (int e = 0; e < dg; e++) {
        int u = g_srcs[st + e];
        const float* hrow = &g_hs2[u * DD];
        float4 hs[6];
        float s = 0.f;
#pragma unroll
        for (int i = 0; i < 6; i++) {
            hs[i] = *(const float4*)&hrow[i * 128 + jb];
            float4 a = *(const float4*)&at_sh[i * 128 + jb];
            s += lrelu(hs[i].x + hd[i].x) * a.x + lrelu(hs[i].y + hd[i].y) * a.y
               + lrelu(hs[i].z + hd[i].z) * a.z + lrelu(hs[i].w + hd[i].w) * a.w;
        }
#pragma unroll
        for (int o = 16; o; o >>= 1) s += __shfl_xor_sync(0xffffffffu, s, o);
        float nm = fmaxf(m, s);
        float c = __expf(m - nm);
        float p = __expf(s - nm);
        den = den * c + p;
#pragma unroll
        for (int i = 0; i < 6; i++) {
            acc[i].x = acc[i].x * c + p * hs[i].x;
            acc[i].y = acc[i].y * c + p * hs[i].y;
            acc[i].z = acc[i].z * c + p * hs[i].z;
            acc[i].w = acc[i].w * c + p * hs[i].w;
        }
        m = nm;
    }
    float inv = 1.f / den;
#pragma unroll
    for (int i = 0; i < 6; i++) {
        float4 o = make_float4(acc[i].x * inv, acc[i].y * inv, acc[i].z * inv, acc[i].w * inv);
        *(float4*)&g_emb[v * DD + i * 128 + jb] = o;
    }
}

// ---------------- positional embedding ----------------
__global__ void k_pe() {
    int idx = blockIdx.x * blockDim.x + threadIdx.x;
    if (idx >= SS * DD) return;
    int s = idx / DD, d = idx % DD;
    int i2 = d >> 1;
    float div = __expf((float)(2 * i2) * (-9.210340371976184f / (float)DD));
    float ang = (float)s * div;
    g_pe[idx] = (d & 1) ? cosf(ang) : sinf(ang);
}

// ---------------- final gather + sum ----------------
__global__ void k_out(const int* __restrict__ trj, const int* __restrict__ mins,
                      const int* __restrict__ wkd, const int* __restrict__ day,
                      const int* __restrict__ grd,
                      const float* __restrict__ grid_tab, const float* __restrict__ dayt_tab,
                      const float* __restrict__ wk_tab, const float* __restrict__ day_tab,
                      float* __restrict__ out) {
    int r = blockIdx.x;
    int tok = trj[r], mn = mins[r], wk = wkd[r], dy = day[r], gd = grd[r];
    int s = r & (SS - 1);
    int j = threadIdx.x * 4;
    float4 a = *(const float4*)&g_pe[s * DD + j];
    float4 b = *(const float4*)&g_emb[tok * DD + j];
    float4 c = *(const float4*)&wk_tab[wk * DD + j];
    float4 d = *(const float4*)&dayt_tab[mn * DD + j];
    float4 e = *(const float4*)&day_tab[dy * DD + j];
    float4 f = *(const float4*)&grid_tab[gd * DD + j];
    float4 o;
    o.x = a.x + b.x + c.x + d.x + e.x + f.x;
    o.y = a.y + b.y + c.y + d.y + e.y + f.y;
    o.z = a.z + b.z + c.z + d.z + e.z + f.z;
    o.w = a.w + b.w + c.w + d.w + e.w + f.w;
    *(float4*)&out[r * DD + j] = o;
}

// ---------------- launch ----------------
extern "C" void kernel_launch(void* const* d_in, const int* in_sizes, int n_in,
                              void* d_out, int out_size) {
    const int*   trj      = (const int*)d_in[0];
    const int*   min_list = (const int*)d_in[1];
    const int*   wkd_list = (const int*)d_in[2];
    const int*   day_list = (const int*)d_in[3];
    const int*   grd_list = (const int*)d_in[4];
    const int*   e_src    = (const int*)d_in[6];
    const int*   e_dst    = (const int*)d_in[7];
    const float* feat     = (const float*)d_in[8];
    const float* W_src1   = (const float*)d_in[9];
    const float* W_dst1   = (const float*)d_in[10];
    const float* attn1    = (const float*)d_in[11];
    const float* W_src2   = (const float*)d_in[12];
    const float* W_dst2   = (const float*)d_in[13];
    const float* attn2    = (const float*)d_in[14];
    const float* grid_tab = (const float*)d_in[15];
    const float* dayt_tab = (const float*)d_in[16];
    const float* wk_tab   = (const float*)d_in[17];
    const float* day_tab  = (const float*)d_in[18];
    float* out = (float*)d_out;

    const int smem_bytes = 4 * 128 * STRD * 2;   // 139264
    cudaFuncSetAttribute(k_gemm2_mma, cudaFuncAttributeMaxDynamicSharedMemorySize, smem_bytes);

    __nv_bfloat16 *wsh, *wsl, *wdh, *wdl;
    cudaGetSymbolAddress((void**)&wsh, g_wsh);
    cudaGetSymbolAddress((void**)&wsl, g_wsl);
    cudaGetSymbolAddress((void**)&wdh, g_wdh);
    cudaGetSymbolAddress((void**)&wdl, g_wdl);
    float *hs2, *hd2;
    cudaGetSymbolAddress((void**)&hs2, g_hs2);
    cudaGetSymbolAddress((void**)&hd2, g_hd2);

    k_init<<<80, 256>>>();
    k_gemm1<<<(NN + 15) / 16, 128>>>(feat, W_src1, W_dst1);
    k_hist<<<352, 512>>>(e_dst);
    k_scan<<<1, 1024>>>();
    k_scatter<<<352, 512>>>(e_src, e_dst);
    k_layer1<<<(NN + 7) / 8, 256>>>(attn1);      // <- ncu -s 5 profiles this
    k_wsplit<<<(DD * HH + 255) / 256, 256>>>(W_src2, W_dst2);
    k_pe<<<(SS * DD + 255) / 256, 256>>>();
    k_flag<<<32, 256>>>(trj);
    dim3 g2(DD / 128, (NN + 127) / 128);
    k_gemm2_mma<<<g2, 256, smem_bytes>>>(wsh, wsl, hs2, 0);
    k_gemm2_mma<<<g2, 256, smem_bytes>>>(wdh, wdl, hd2, 1);
    k_layer2<<<(NN + 7) / 8, 256>>>(attn2);
    k_out<<<BS, 192>>>(trj, min_list, wkd_list, day_list, grd_list,
                       grid_tab, dayt_tab, wk_tab, day_tab, out);
}

// round 4
// speedup vs baseline: 1.4833x; 1.1050x over previous
#include <cuda_runtime.h>
#include <cuda_bf16.h>
#include <math.h>
#include <stdint.h>

#define NN 20000
#define EE 180000
#define DD 768
#define SS 512
#define BS 8192      // B*S
#define HH 128       // HEADS*HID
#define STRD 136     // padded SMEM row stride (bf16 elems)

// ---------------- scratch (device globals; no runtime alloc) ----------------
__device__ float g_hs1[NN * HH];
__device__ float g_hd1[NN * HH];
__device__ __nv_bfloat16 g_h1h[NN * HH];
__device__ __nv_bfloat16 g_h1l[NN * HH];
__device__ __nv_bfloat16 g_wsh[DD * HH];
__device__ __nv_bfloat16 g_wsl[DD * HH];
__device__ __nv_bfloat16 g_wdh[DD * HH];
__device__ __nv_bfloat16 g_wdl[DD * HH];
__device__ float g_hs2[NN * DD];
__device__ float g_hd2[NN * DD];
__device__ float g_emb[NN * DD];
__device__ float g_pe [SS * DD];
__device__ int   g_deg[NN];
__device__ int   g_off[NN];
__device__ int   g_cur[NN];
__device__ int   g_flag[NN];
__device__ int   g_list[NN];
__device__ int   g_srcs[EE];
__device__ int   g_cnt;

__device__ __forceinline__ float lrelu(float x) { return x > 0.f ? x : 0.2f * x; }
__device__ __forceinline__ float elu1(float x)  { return x > 0.f ? x : expm1f(x); }

__device__ __forceinline__ uint32_t smem_u32(const void* p) {
    uint32_t a;
    asm("{ .reg .u64 t; cvta.to.shared.u64 t, %1; cvt.u32.u64 %0, t; }" : "=r"(a) : "l"(p));
    return a;
}

#define LDSM_X4(r0, r1, r2, r3, addr) \
    asm volatile("ldmatrix.sync.aligned.m8n8.x4.shared.b16 {%0,%1,%2,%3}, [%4];" \
                 : "=r"(r0), "=r"(r1), "=r"(r2), "=r"(r3) : "r"(addr))

#define MMA16816(c, a0, a1, a2, a3, b0, b1) \
    asm volatile("mma.sync.aligned.m16n8k16.row.col.f32.bf16.bf16.f32 " \
                 "{%0,%1,%2,%3}, {%4,%5,%6,%7}, {%8,%9}, {%0,%1,%2,%3};" \
                 : "+f"((c)[0]), "+f"((c)[1]), "+f"((c)[2]), "+f"((c)[3]) \
                 : "r"(a0), "r"(a1), "r"(a2), "r"(a3), "r"(b0), "r"(b1))

// ---------------- init ----------------
__global__ void k_init() {
    int i = blockIdx.x * blockDim.x + threadIdx.x;
    int stride = gridDim.x * blockDim.x;
    for (int j = i; j < NN; j += stride) { g_deg[j] = 0; g_cur[j] = 0; g_flag[j] = 0; }
    if (i == 0) g_cnt = 0;
}

// ---------------- CSR build ----------------
__global__ void k_hist(const int* __restrict__ dst) {
    int i = blockIdx.x * blockDim.x + threadIdx.x;
    int stride = gridDim.x * blockDim.x;
    for (int e = i; e < EE; e += stride) atomicAdd(&g_deg[dst[e]], 1);
}

// fast single-block exclusive scan: 1024 threads x 20 serial elements
__global__ void k_scan() {
    __shared__ int wsum[32];
    const int t = threadIdx.x;
    const int PER = (NN + 1023) / 1024;     // 20
    const int base = t * PER;
    int pre[PER];
    int local = 0;
#pragma unroll
    for (int i = 0; i < PER; i++) {
        int idx = base + i;
        int v = (idx < NN) ? g_deg[idx] : 0;
        pre[i] = local;
        local += v;
    }
    const int lane = t & 31, wid = t >> 5;
    int x = local;
#pragma unroll
    for (int o = 1; o < 32; o <<= 1) {
        int y = __shfl_up_sync(0xffffffffu, x, o);
        if (lane >= o) x += y;
    }
    if (lane == 31) wsum[wid] = x;
    __syncthreads();
    if (wid == 0) {
        int s = wsum[lane];
#pragma unroll
        for (int o = 1; o < 32; o <<= 1) {
            int y = __shfl_up_sync(0xffffffffu, s, o);
            if (lane >= o) s += y;
        }
        wsum[lane] = s;
    }
    __syncthreads();
    int texcl = (x - local) + (wid > 0 ? wsum[wid - 1] : 0);
#pragma unroll
    for (int i = 0; i < PER; i++) {
        int idx = base + i;
        if (idx < NN) g_off[idx] = texcl + pre[i];
    }
}

__global__ void k_scatter(const int* __restrict__ src, const int* __restrict__ dst) {
    int i = blockIdx.x * blockDim.x + threadIdx.x;
    int stride = gridDim.x * blockDim.x;
    for (int e = i; e < EE; e += stride) {
        int d = dst[e];
        int pos = g_off[d] + atomicAdd(&g_cur[d], 1);
        g_srcs[pos] = src[e];
    }
}

// ---------------- layer-1 input projections ----------------
__global__ void k_gemm1(const float* __restrict__ feat,
                        const float* __restrict__ Ws, const float* __restrict__ Wd) {
    __shared__ float ws[4 * HH], wd[4 * HH];
    int t = threadIdx.x;                     // 128
    for (int i = t; i < 4 * HH; i += 128) { ws[i] = Ws[i]; wd[i] = Wd[i]; }
    __syncthreads();
    int n0 = blockIdx.x * 16;
    int n1 = min(NN, n0 + 16);
    for (int n = n0; n < n1; n++) {
        float f0 = feat[n * 4 + 0], f1 = feat[n * 4 + 1], f2 = feat[n * 4 + 2], f3 = feat[n * 4 + 3];
        float s = f0 * ws[t] + f1 * ws[HH + t] + f2 * ws[2 * HH + t] + f3 * ws[3 * HH + t];
        float d = f0 * wd[t] + f1 * wd[HH + t] + f2 * wd[2 * HH + t] + f3 * wd[3 * HH + t];
        g_hs1[n * HH + t] = s;
        g_hd1[n * HH + t] = d;
    }
}

// ---------------- layer-1: warp per node, online softmax; emit bf16 hi/lo ----------------
__global__ void k_layer1(const float* __restrict__ attn1) {
    int v = (blockIdx.x << 3) + (threadIdx.x >> 5);
    if (v >= NN) return;
    int lane = threadIdx.x & 31;
    int jb = lane * 4;

    float4 hd = *(const float4*)&g_hd1[v * HH + jb];
    float4 at = *(const float4*)&attn1[jb];
    float4 acc = make_float4(0.f, 0.f, 0.f, 0.f);
    float m = -INFINITY, den = 0.f;

    int st = g_off[v], dg = g_deg[v];
    for (int e = 0; e < dg; e++) {
        int u = g_srcs[st + e];
        float4 hs = *(const float4*)&g_hs1[u * HH + jb];
        float s = lrelu(hs.x + hd.x) * at.x + lrelu(hs.y + hd.y) * at.y
                + lrelu(hs.z + hd.z) * at.z + lrelu(hs.w + hd.w) * at.w;
        s += __shfl_xor_sync(0xffffffffu, s, 1);
        s += __shfl_xor_sync(0xffffffffu, s, 2);
        float nm = fmaxf(m, s);
        float c = __expf(m - nm);
        float p = __expf(s - nm);
        den = den * c + p;
        acc.x = acc.x * c + p * hs.x;
        acc.y = acc.y * c + p * hs.y;
        acc.z = acc.z * c + p * hs.z;
        acc.w = acc.w * c + p * hs.w;
        m = nm;
    }
    float inv = 1.f / den;
    float o[4];
    o[0] = elu1(acc.x * inv); o[1] = elu1(acc.y * inv);
    o[2] = elu1(acc.z * inv); o[3] = elu1(acc.w * inv);
#pragma unroll
    for (int i = 0; i < 4; i++) {
        __nv_bfloat16 h = __float2bfloat16(o[i]);
        g_h1h[v * HH + jb + i] = h;
        g_h1l[v * HH + jb + i] = __float2bfloat16(o[i] - __bfloat162float(h));
    }
}

// ---------------- fused: pe (1536 blocks) + wsplit (384) + flag (32) ----------------
__global__ void k_misc(const float* __restrict__ Ws, const float* __restrict__ Wd,
                       const int* __restrict__ trj) {
    int b = blockIdx.x;
    if (b < 1536) {
        int idx = b * 256 + threadIdx.x;
        int s = idx / DD, d = idx % DD;
        int i2 = d >> 1;
        float div = __expf((float)(2 * i2) * (-9.210340371976184f / (float)DD));
        float ang = (float)s * div;
        g_pe[idx] = (d & 1) ? cosf(ang) : sinf(ang);
    } else if (b < 1536 + 384) {
        int i = (b - 1536) * 256 + threadIdx.x;
        int n = i >> 7, k = i & 127;
        float ws = Ws[k * DD + n];
        __nv_bfloat16 h = __float2bfloat16(ws);
        g_wsh[i] = h;
        g_wsl[i] = __float2bfloat16(ws - __bfloat162float(h));
        float wd = Wd[k * DD + n];
        h = __float2bfloat16(wd);
        g_wdh[i] = h;
        g_wdl[i] = __float2bfloat16(wd - __bfloat162float(h));
    } else {
        int j = (b - 1536 - 384) * 256 + threadIdx.x;
        if (j < BS) {
            int tok = trj[j];
            if (atomicExch(&g_flag[tok], 1) == 0) {
                int p = atomicAdd(&g_cnt, 1);
                g_list[p] = tok;
            }
        }
    }
}

// ---------------- layer-2 GEMM via mma.sync bf16x3 (merged both planes) ----------------
// z==0: C=hs2 over all NN rows with (Bh0,Bl0); z==1: C=hd2 over g_cnt listed rows with (Bh1,Bl1)
__global__ void __launch_bounds__(256, 1) k_gemm2_mma(
        const __nv_bfloat16* __restrict__ Bh0, const __nv_bfloat16* __restrict__ Bl0,
        const __nv_bfloat16* __restrict__ Bh1, const __nv_bfloat16* __restrict__ Bl1,
        float* __restrict__ C0, float* __restrict__ C1) {
    extern __shared__ __nv_bfloat16 sm[];
    __nv_bfloat16* Ah_s = sm;
    __nv_bfloat16* Al_s = sm + 128 * STRD;
    __nv_bfloat16* Bh_s = sm + 2 * 128 * STRD;
    __nv_bfloat16* Bl_s = sm + 3 * 128 * STRD;

    const int use_list = blockIdx.z;
    const int M_eff = use_list ? g_cnt : NN;
    const int bm = blockIdx.y, bn = blockIdx.x;
    if (bm * 128 >= M_eff) return;
    const __nv_bfloat16* Bh = use_list ? Bh1 : Bh0;
    const __nv_bfloat16* Bl = use_list ? Bl1 : Bl0;
    float* C = use_list ? C1 : C0;
    const int row0 = bm * 128, n0 = bn * 128;
    const int tid = threadIdx.x;

    const uint4 z4 = make_uint4(0, 0, 0, 0);
    for (int i = tid; i < 2048; i += 256) {
        int r = i >> 4, ck = i & 15;
        int so = r * STRD + ck * 8;
        int gr = row0 + r;
        uint4 vh = z4, vl = z4;
        if (gr < M_eff) {
            int rr = use_list ? g_list[gr] : gr;
            vh = *(const uint4*)&g_h1h[rr * HH + ck * 8];
            vl = *(const uint4*)&g_h1l[rr * HH + ck * 8];
        }
        *(uint4*)&Ah_s[so] = vh;
        *(uint4*)&Al_s[so] = vl;
        int gn = n0 + r;
        *(uint4*)&Bh_s[so] = *(const uint4*)&Bh[gn * HH + ck * 8];
        *(uint4*)&Bl_s[so] = *(const uint4*)&Bl[gn * HH + ck * 8];
    }
    __syncthreads();

    const int wid = tid >> 5, lane = tid & 31;
    const int wm = (wid >> 1) * 32, wn = (wid & 1) * 64;

    float acc[2][8][4];
#pragma unroll
    for (int mt = 0; mt < 2; mt++)
#pragma unroll
        for (int nt = 0; nt < 8; nt++)
#pragma unroll
            for (int c = 0; c < 4; c++) acc[mt][nt][c] = 0.f;

    const int a_row = wm + (lane & 15);
    const int a_kof = (lane >> 4) * 8;
    const int q = lane >> 3, rrow = lane & 7;
    const int b_nof = ((q >> 1) ? 8 : 0) + rrow;
    const int b_kof = (q & 1) * 8;

    const uint32_t sAh = smem_u32(Ah_s), sAl = smem_u32(Al_s);
    const uint32_t sBh = smem_u32(Bh_s), sBl = smem_u32(Bl_s);

#pragma unroll
    for (int ks = 0; ks < 8; ks++) {
        const int kbase = ks * 16;
        uint32_t ah[2][4], al[2][4], bh[8][2], bl[8][2];
#pragma unroll
        for (int mt = 0; mt < 2; mt++) {
            uint32_t ad = sAh + ((a_row + mt * 16) * STRD + kbase + a_kof) * 2;
            LDSM_X4(ah[mt][0], ah[mt][1], ah[mt][2], ah[mt][3], ad);
        }
#pragma unroll
        for (int np = 0; np < 4; np++) {
            uint32_t bd = sBh + ((wn + np * 16 + b_nof) * STRD + kbase + b_kof) * 2;
            LDSM_X4(bh[np * 2][0], bh[np * 2][1], bh[np * 2 + 1][0], bh[np * 2 + 1][1], bd);
        }
#pragma unroll
        for (int mt = 0; mt < 2; mt++)
#pragma unroll
            for (int nt = 0; nt < 8; nt++)
                MMA16816(acc[mt][nt], ah[mt][0], ah[mt][1], ah[mt][2], ah[mt][3],
                         bh[nt][0], bh[nt][1]);
#pragma unroll
        for (int mt = 0; mt < 2; mt++) {
            uint32_t ad = sAl + ((a_row + mt * 16) * STRD + kbase + a_kof) * 2;
            LDSM_X4(al[mt][0], al[mt][1], al[mt][2], al[mt][3], ad);
        }
#pragma unroll
        for (int mt = 0; mt < 2; mt++)
#pragma unroll
            for (int nt = 0; nt < 8; nt++)
                MMA16816(acc[mt][nt], al[mt][0], al[mt][1], al[mt][2], al[mt][3],
                         bh[nt][0], bh[nt][1]);
#pragma unroll
        for (int np = 0; np < 4; np++) {
            uint32_t bd = sBl + ((wn + np * 16 + b_nof) * STRD + kbase + b_kof) * 2;
            LDSM_X4(bl[np * 2][0], bl[np * 2][1], bl[np * 2 + 1][0], bl[np * 2 + 1][1], bd);
        }
#pragma unroll
        for (int mt = 0; mt < 2; mt++)
#pragma unroll
            for (int nt = 0; nt < 8; nt++)
                MMA16816(acc[mt][nt], ah[mt][0], ah[mt][1], ah[mt][2], ah[mt][3],
                         bl[nt][0], bl[nt][1]);
    }

    const int gid = lane >> 2, tig = lane & 3;
#pragma unroll
    for (int mt = 0; mt < 2; mt++) {
        int grow0 = row0 + wm + mt * 16 + gid;
        int grow1 = grow0 + 8;
        bool v0 = grow0 < M_eff, v1 = grow1 < M_eff;
        int rr0 = v0 ? (use_list ? g_list[grow0] : grow0) : 0;
        int rr1 = v1 ? (use_list ? g_list[grow1] : grow1) : 0;
#pragma unroll
        for (int nt = 0; nt < 8; nt++) {
            int col = n0 + wn + nt * 8 + tig * 2;
            if (v0) *(float2*)&C[(size_t)rr0 * DD + col] = make_float2(acc[mt][nt][0], acc[mt][nt][1]);
            if (v1) *(float2*)&C[(size_t)rr1 * DD + col] = make_float2(acc[mt][nt][2], acc[mt][nt][3]);
        }
    }
}

// ---------------- layer-2: warp per flagged node, online softmax ----------------
__global__ void k_layer2(const float* __restrict__ attn2) {
    __shared__ float at_sh[DD];
    for (int i = threadIdx.x; i < DD; i += 256) at_sh[i] = attn2[i];
    __syncthreads();

    int v = (blockIdx.x << 3) + (threadIdx.x >> 5);
    if (v >= NN || !g_flag[v]) return;
    int lane = threadIdx.x & 31;
    int jb = lane * 4;

    float4 hd[6], acc[6];
#pragma unroll
    for (int i = 0; i < 6; i++) {
        hd[i] = *(const float4*)&g_hd2[v * DD + i * 128 + jb];
        acc[i] = make_float4(0.f, 0.f, 0.f, 0.f);
    }
    float m = -INFINITY, den = 0.f;

    int st = g_off[v], dg = g_deg[v];
    for (int e = 0; e < dg; e++) {
        int u = g_srcs[st + e];
        const float* hrow = &g_hs2[u * DD];
        float4 hs[6];
        float s = 0.f;
#pragma unroll
        for (int i = 0; i < 6; i++) {
            hs[i] = *(const float4*)&hrow[i * 128 + jb];
            float4 a = *(const float4*)&at_sh[i * 128 + jb];
            s += lrelu(hs[i].x + hd[i].x) * a.x + lrelu(hs[i].y + hd[i].y) * a.y
               + lrelu(hs[i].z + hd[i].z) * a.z + lrelu(hs[i].w + hd[i].w) * a.w;
        }
#pragma unroll
        for (int o = 16; o; o >>= 1) s += __shfl_xor_sync(0xffffffffu, s, o);
        float nm = fmaxf(m, s);
        float c = __expf(m - nm);
        float p = __expf(s - nm);
        den = den * c + p;
#pragma unroll
        for (int i = 0; i < 6; i++) {
            acc[i].x = acc[i].x * c + p * hs[i].x;
            acc[i].y = acc[i].y * c + p * hs[i].y;
            acc[i].z = acc[i].z * c + p * hs[i].z;
            acc[i].w = acc[i].w * c + p * hs[i].w;
        }
        m = nm;
    }
    float inv = 1.f / den;
#pragma unroll
    for (int i = 0; i < 6; i++) {
        float4 o = make_float4(acc[i].x * inv, acc[i].y * inv, acc[i].z * inv, acc[i].w * inv);
        *(float4*)&g_emb[v * DD + i * 128 + jb] = o;
    }
}

// ---------------- final gather + sum ----------------
__global__ void k_out(const int* __restrict__ trj, const int* __restrict__ mins,
                      const int* __restrict__ wkd, const int* __restrict__ day,
                      const int* __restrict__ grd,
                      const float* __restrict__ grid_tab, const float* __restrict__ dayt_tab,
                      const float* __restrict__ wk_tab, const float* __restrict__ day_tab,
                      float* __restrict__ out) {
    int r = blockIdx.x;
    int tok = trj[r], mn = mins[r], wk = wkd[r], dy = day[r], gd = grd[r];
    int s = r & (SS - 1);
    int j = threadIdx.x * 4;
    float4 a = *(const float4*)&g_pe[s * DD + j];
    float4 b = *(const float4*)&g_emb[tok * DD + j];
    float4 c = *(const float4*)&wk_tab[wk * DD + j];
    float4 d = *(const float4*)&dayt_tab[mn * DD + j];
    float4 e = *(const float4*)&day_tab[dy * DD + j];
    float4 f = *(const float4*)&grid_tab[gd * DD + j];
    float4 o;
    o.x = a.x + b.x + c.x + d.x + e.x + f.x;
    o.y = a.y + b.y + c.y + d.y + e.y + f.y;
    o.z = a.z + b.z + c.z + d.z + e.z + f.z;
    o.w = a.w + b.w + c.w + d.w + e.w + f.w;
    *(float4*)&out[r * DD + j] = o;
}

// ---------------- launch ----------------
extern "C" void kernel_launch(void* const* d_in, const int* in_sizes, int n_in,
                              void* d_out, int out_size) {
    const int*   trj      = (const int*)d_in[0];
    const int*   min_list = (const int*)d_in[1];
    const int*   wkd_list = (const int*)d_in[2];
    const int*   day_list = (const int*)d_in[3];
    const int*   grd_list = (const int*)d_in[4];
    const int*   e_src    = (const int*)d_in[6];
    const int*   e_dst    = (const int*)d_in[7];
    const float* feat     = (const float*)d_in[8];
    const float* W_src1   = (const float*)d_in[9];
    const float* W_dst1   = (const float*)d_in[10];
    const float* attn1    = (const float*)d_in[11];
    const float* W_src2   = (const float*)d_in[12];
    const float* W_dst2   = (const float*)d_in[13];
    const float* attn2    = (const float*)d_in[14];
    const float* grid_tab = (const float*)d_in[15];
    const float* dayt_tab = (const float*)d_in[16];
    const float* wk_tab   = (const float*)d_in[17];
    const float* day_tab  = (const float*)d_in[18];
    float* out = (float*)d_out;

    const int smem_bytes = 4 * 128 * STRD * 2;   // 139264
    cudaFuncSetAttribute(k_gemm2_mma, cudaFuncAttributeMaxDynamicSharedMemorySize, smem_bytes);

    __nv_bfloat16 *wsh, *wsl, *wdh, *wdl;
    cudaGetSymbolAddress((void**)&wsh, g_wsh);
    cudaGetSymbolAddress((void**)&wsl, g_wsl);
    cudaGetSymbolAddress((void**)&wdh, g_wdh);
    cudaGetSymbolAddress((void**)&wdl, g_wdl);
    float *hs2, *hd2;
    cudaGetSymbolAddress((void**)&hs2, g_hs2);
    cudaGetSymbolAddress((void**)&hd2, g_hd2);

    k_init<<<80, 256>>>();                                    // 0
    k_hist<<<352, 512>>>(e_dst);                              // 1
    k_scan<<<1, 1024>>>();                                    // 2
    k_scatter<<<352, 512>>>(e_src, e_dst);                    // 3  <- profiled
    k_gemm1<<<(NN + 15) / 16, 128>>>(feat, W_src1, W_dst1);   // 4
    k_misc<<<1536 + 384 + 32, 256>>>(W_src2, W_dst2, trj);    // 5
    k_layer1<<<(NN + 7) / 8, 256>>>(attn1);                   // 6
    dim3 g2(DD / 128, (NN + 127) / 128, 2);
    k_gemm2_mma<<<g2, 256, smem_bytes>>>(wsh, wsl, wdh, wdl, hs2, hd2);
    k_layer2<<<(NN + 7) / 8, 256>>>(attn2);
    k_out<<<BS, 192>>>(trj, min_list, wkd_list, day_list, grd_list,
                       grid_tab, dayt_tab, wk_tab, day_tab, out);
}

// round 5
// speedup vs baseline: 1.8496x; 1.2469x over previous
#include <cuda_runtime.h>
#include <cuda_bf16.h>
#include <math.h>
#include <stdint.h>

#define NN 20000
#define EE 180000
#define DD 768
#define SS 512
#define BS 8192      // B*S
#define HH 128       // HEADS*HID
#define STRD 136     // padded SMEM row stride (bf16 elems)

// ---------------- scratch (device globals; no runtime alloc) ----------------
__device__ float g_hs1[NN * HH];
__device__ float g_hd1[NN * HH];
__device__ __nv_bfloat16 g_h1h[NN * HH];
__device__ __nv_bfloat16 g_h1l[NN * HH];
__device__ __nv_bfloat16 g_wsh[DD * HH];
__device__ __nv_bfloat16 g_wsl[DD * HH];
__device__ __nv_bfloat16 g_wdh[DD * HH];
__device__ __nv_bfloat16 g_wdl[DD * HH];
__device__ float g_hs2[NN * DD];
__device__ float g_hd2[NN * DD];
__device__ float g_emb[NN * DD];
__device__ float g_pe [SS * DD];
__device__ int   g_deg[NN];
__device__ int   g_off[NN];
__device__ int   g_cur[NN];
__device__ int   g_flag[NN];
__device__ int   g_list[NN];
__device__ int   g_srcs[EE];
__device__ int   g_cnt;

__device__ __forceinline__ float lrelu(float x) { return x > 0.f ? x : 0.2f * x; }
__device__ __forceinline__ float elu1(float x)  { return x > 0.f ? x : expm1f(x); }

__device__ __forceinline__ uint32_t smem_u32(const void* p) {
    uint32_t a;
    asm("{ .reg .u64 t; cvta.to.shared.u64 t, %1; cvt.u32.u64 %0, t; }" : "=r"(a) : "l"(p));
    return a;
}

#define LDSM_X4(r0, r1, r2, r3, addr) \
    asm volatile("ldmatrix.sync.aligned.m8n8.x4.shared.b16 {%0,%1,%2,%3}, [%4];" \
                 : "=r"(r0), "=r"(r1), "=r"(r2), "=r"(r3) : "r"(addr))

#define MMA16816(c, a0, a1, a2, a3, b0, b1) \
    asm volatile("mma.sync.aligned.m16n8k16.row.col.f32.bf16.bf16.f32 " \
                 "{%0,%1,%2,%3}, {%4,%5,%6,%7}, {%8,%9}, {%0,%1,%2,%3};" \
                 : "+f"((c)[0]), "+f"((c)[1]), "+f"((c)[2]), "+f"((c)[3]) \
                 : "r"(a0), "r"(a1), "r"(a2), "r"(a3), "r"(b0), "r"(b1))

// ---------------- init ----------------
__global__ void k_init() {
    int i = blockIdx.x * blockDim.x + threadIdx.x;
    int stride = gridDim.x * blockDim.x;
    for (int j = i; j < NN; j += stride) { g_deg[j] = 0; g_cur[j] = 0; g_flag[j] = 0; }
    if (i == 0) g_cnt = 0;
}

// ---------------- CSR build ----------------
__global__ void k_hist(const int* __restrict__ dst) {
    int i = blockIdx.x * blockDim.x + threadIdx.x;
    int stride = gridDim.x * blockDim.x;
    for (int e = i; e < EE; e += stride) atomicAdd(&g_deg[dst[e]], 1);
}

// fast single-block exclusive scan: 1024 threads x 20 serial elements
__global__ void k_scan() {
    __shared__ int wsum[32];
    const int t = threadIdx.x;
    const int PER = (NN + 1023) / 1024;     // 20
    const int base = t * PER;
    int pre[PER];
    int local = 0;
#pragma unroll
    for (int i = 0; i < PER; i++) {
        int idx = base + i;
        int v = (idx < NN) ? g_deg[idx] : 0;
        pre[i] = local;
        local += v;
    }
    const int lane = t & 31, wid = t >> 5;
    int x = local;
#pragma unroll
    for (int o = 1; o < 32; o <<= 1) {
        int y = __shfl_up_sync(0xffffffffu, x, o);
        if (lane >= o) x += y;
    }
    if (lane == 31) wsum[wid] = x;
    __syncthreads();
    if (wid == 0) {
        int s = wsum[lane];
#pragma unroll
        for (int o = 1; o < 32; o <<= 1) {
            int y = __shfl_up_sync(0xffffffffu, s, o);
            if (lane >= o) s += y;
        }
        wsum[lane] = s;
    }
    __syncthreads();
    int texcl = (x - local) + (wid > 0 ? wsum[wid - 1] : 0);
#pragma unroll
    for (int i = 0; i < PER; i++) {
        int idx = base + i;
        if (idx < NN) g_off[idx] = texcl + pre[i];
    }
}

__global__ void k_scatter(const int* __restrict__ src, const int* __restrict__ dst) {
    int i = blockIdx.x * blockDim.x + threadIdx.x;
    int stride = gridDim.x * blockDim.x;
    for (int e = i; e < EE; e += stride) {
        int d = dst[e];
        int pos = g_off[d] + atomicAdd(&g_cur[d], 1);
        g_srcs[pos] = src[e];
    }
}

// ---------------- layer-1 input projections ----------------
__global__ void k_gemm1(const float* __restrict__ feat,
                        const float* __restrict__ Ws, const float* __restrict__ Wd) {
    __shared__ float ws[4 * HH], wd[4 * HH];
    int t = threadIdx.x;                     // 128
    for (int i = t; i < 4 * HH; i += 128) { ws[i] = Ws[i]; wd[i] = Wd[i]; }
    __syncthreads();
    int n0 = blockIdx.x * 16;
    int n1 = min(NN, n0 + 16);
    for (int n = n0; n < n1; n++) {
        float f0 = feat[n * 4 + 0], f1 = feat[n * 4 + 1], f2 = feat[n * 4 + 2], f3 = feat[n * 4 + 3];
        float s = f0 * ws[t] + f1 * ws[HH + t] + f2 * ws[2 * HH + t] + f3 * ws[3 * HH + t];
        float d = f0 * wd[t] + f1 * wd[HH + t] + f2 * wd[2 * HH + t] + f3 * wd[3 * HH + t];
        g_hs1[n * HH + t] = s;
        g_hd1[n * HH + t] = d;
    }
}

// ---------------- layer-1: warp per node, online softmax; emit bf16 hi/lo ----------------
__global__ void k_layer1(const float* __restrict__ attn1) {
    int v = (blockIdx.x << 3) + (threadIdx.x >> 5);
    if (v >= NN) return;
    int lane = threadIdx.x & 31;
    int jb = lane * 4;

    float4 hd = *(const float4*)&g_hd1[v * HH + jb];
    float4 at = *(const float4*)&attn1[jb];
    float4 acc = make_float4(0.f, 0.f, 0.f, 0.f);
    float m = -INFINITY, den = 0.f;

    int st = g_off[v], dg = g_deg[v];
    for (int e = 0; e < dg; e++) {
        int u = g_srcs[st + e];
        float4 hs = *(const float4*)&g_hs1[u * HH + jb];
        float s = lrelu(hs.x + hd.x) * at.x + lrelu(hs.y + hd.y) * at.y
                + lrelu(hs.z + hd.z) * at.z + lrelu(hs.w + hd.w) * at.w;
        s += __shfl_xor_sync(0xffffffffu, s, 1);
        s += __shfl_xor_sync(0xffffffffu, s, 2);
        float nm = fmaxf(m, s);
        float c = __expf(m - nm);
        float p = __expf(s - nm);
        den = den * c + p;
        acc.x = acc.x * c + p * hs.x;
        acc.y = acc.y * c + p * hs.y;
        acc.z = acc.z * c + p * hs.z;
        acc.w = acc.w * c + p * hs.w;
        m = nm;
    }
    float inv = 1.f / den;
    float o[4];
    o[0] = elu1(acc.x * inv); o[1] = elu1(acc.y * inv);
    o[2] = elu1(acc.z * inv); o[3] = elu1(acc.w * inv);
#pragma unroll
    for (int i = 0; i < 4; i++) {
        __nv_bfloat16 h = __float2bfloat16(o[i]);
        g_h1h[v * HH + jb + i] = h;
        g_h1l[v * HH + jb + i] = __float2bfloat16(o[i] - __bfloat162float(h));
    }
}

// ---------------- fused: pe (1536 blocks) + wsplit (384) + flag (32) ----------------
__global__ void k_misc(const float* __restrict__ Ws, const float* __restrict__ Wd,
                       const int* __restrict__ trj) {
    int b = blockIdx.x;
    if (b < 1536) {
        int idx = b * 256 + threadIdx.x;
        int s = idx / DD, d = idx % DD;
        int i2 = d >> 1;
        float div = __expf((float)(2 * i2) * (-9.210340371976184f / (float)DD));
        float ang = (float)s * div;
        g_pe[idx] = (d & 1) ? cosf(ang) : sinf(ang);
    } else if (b < 1536 + 384) {
        int i = (b - 1536) * 256 + threadIdx.x;
        int n = i >> 7, k = i & 127;
        float ws = Ws[k * DD + n];
        __nv_bfloat16 h = __float2bfloat16(ws);
        g_wsh[i] = h;
        g_wsl[i] = __float2bfloat16(ws - __bfloat162float(h));
        float wd = Wd[k * DD + n];
        h = __float2bfloat16(wd);
        g_wdh[i] = h;
        g_wdl[i] = __float2bfloat16(wd - __bfloat162float(h));
    } else {
        int j = (b - 1536 - 384) * 256 + threadIdx.x;
        if (j < BS) {
            int tok = trj[j];
            if (atomicExch(&g_flag[tok], 1) == 0) {
                int p = atomicAdd(&g_cnt, 1);
                g_list[p] = tok;
            }
        }
    }
}

// ---------------- layer-2 GEMM via mma.sync bf16x3, 128x64 tile, occ=2 ----------------
// z==0: C=hs2 over all NN rows with (Bh0,Bl0); z==1: C=hd2 over g_cnt listed rows with (Bh1,Bl1)
__global__ void __launch_bounds__(256, 2) k_gemm2_mma(
        const __nv_bfloat16* __restrict__ Bh0, const __nv_bfloat16* __restrict__ Bl0,
        const __nv_bfloat16* __restrict__ Bh1, const __nv_bfloat16* __restrict__ Bl1,
        float* __restrict__ C0, float* __restrict__ C1) {
    extern __shared__ __nv_bfloat16 sm[];
    __nv_bfloat16* Ah_s = sm;                       // 128 x STRD
    __nv_bfloat16* Al_s = sm + 128 * STRD;          // 128 x STRD
    __nv_bfloat16* Bh_s = sm + 2 * 128 * STRD;      // 64 x STRD
    __nv_bfloat16* Bl_s = sm + 2 * 128 * STRD + 64 * STRD;

    const int use_list = blockIdx.z;
    const int M_eff = use_list ? g_cnt : NN;
    const int bm = blockIdx.y, bn = blockIdx.x;
    if (bm * 128 >= M_eff) return;
    const __nv_bfloat16* Bh = use_list ? Bh1 : Bh0;
    const __nv_bfloat16* Bl = use_list ? Bl1 : Bl0;
    float* C = use_list ? C1 : C0;
    const int row0 = bm * 128, n0 = bn * 64;
    const int tid = threadIdx.x;

    const uint4 z4 = make_uint4(0, 0, 0, 0);
    for (int i = tid; i < 2048; i += 256) {
        int r = i >> 4, ck = i & 15;
        int so = r * STRD + ck * 8;
        int gr = row0 + r;
        uint4 vh = z4, vl = z4;
        if (gr < M_eff) {
            int rr = use_list ? g_list[gr] : gr;
            vh = *(const uint4*)&g_h1h[rr * HH + ck * 8];
            vl = *(const uint4*)&g_h1l[rr * HH + ck * 8];
        }
        *(uint4*)&Ah_s[so] = vh;
        *(uint4*)&Al_s[so] = vl;
    }
    for (int i = tid; i < 1024; i += 256) {
        int r = i >> 4, ck = i & 15;
        int so = r * STRD + ck * 8;
        int gn = n0 + r;
        *(uint4*)&Bh_s[so] = *(const uint4*)&Bh[gn * HH + ck * 8];
        *(uint4*)&Bl_s[so] = *(const uint4*)&Bl[gn * HH + ck * 8];
    }
    __syncthreads();

    const int wid = tid >> 5, lane = tid & 31;
    const int wm = (wid >> 1) * 32, wn = (wid & 1) * 32;

    float acc[2][4][4];
#pragma unroll
    for (int mt = 0; mt < 2; mt++)
#pragma unroll
        for (int nt = 0; nt < 4; nt++)
#pragma unroll
            for (int c = 0; c < 4; c++) acc[mt][nt][c] = 0.f;

    const int a_row = wm + (lane & 15);
    const int a_kof = (lane >> 4) * 8;
    const int q = lane >> 3, rrow = lane & 7;
    const int b_nof = ((q >> 1) ? 8 : 0) + rrow;
    const int b_kof = (q & 1) * 8;

    const uint32_t sAh = smem_u32(Ah_s), sAl = smem_u32(Al_s);
    const uint32_t sBh = smem_u32(Bh_s), sBl = smem_u32(Bl_s);

#pragma unroll
    for (int ks = 0; ks < 8; ks++) {
        const int kbase = ks * 16;
        uint32_t ah[2][4], al[2][4], bh[4][2], bl[4][2];
#pragma unroll
        for (int mt = 0; mt < 2; mt++) {
            uint32_t ad = sAh + ((a_row + mt * 16) * STRD + kbase + a_kof) * 2;
            LDSM_X4(ah[mt][0], ah[mt][1], ah[mt][2], ah[mt][3], ad);
        }
#pragma unroll
        for (int np = 0; np < 2; np++) {
            uint32_t bd = sBh + ((wn + np * 16 + b_nof) * STRD + kbase + b_kof) * 2;
            LDSM_X4(bh[np * 2][0], bh[np * 2][1], bh[np * 2 + 1][0], bh[np * 2 + 1][1], bd);
        }
#pragma unroll
        for (int mt = 0; mt < 2; mt++)
#pragma unroll
            for (int nt = 0; nt < 4; nt++)
                MMA16816(acc[mt][nt], ah[mt][0], ah[mt][1], ah[mt][2], ah[mt][3],
                         bh[nt][0], bh[nt][1]);
#pragma unroll
        for (int mt = 0; mt < 2; mt++) {
            uint32_t ad = sAl + ((a_row + mt * 16) * STRD + kbase + a_kof) * 2;
            LDSM_X4(al[mt][0], al[mt][1], al[mt][2], al[mt][3], ad);
        }
#pragma unroll
        for (int mt = 0; mt < 2; mt++)
#pragma unroll
            for (int nt = 0; nt < 4; nt++)
                MMA16816(acc[mt][nt], al[mt][0], al[mt][1], al[mt][2], al[mt][3],
                         bh[nt][0], bh[nt][1]);
#pragma unroll
        for (int np = 0; np < 2; np++) {
            uint32_t bd = sBl + ((wn + np * 16 + b_nof) * STRD + kbase + b_kof) * 2;
            LDSM_X4(bl[np * 2][0], bl[np * 2][1], bl[np * 2 + 1][0], bl[np * 2 + 1][1], bd);
        }
#pragma unroll
        for (int mt = 0; mt < 2; mt++)
#pragma unroll
            for (int nt = 0; nt < 4; nt++)
                MMA16816(acc[mt][nt], ah[mt][0], ah[mt][1], ah[mt][2], ah[mt][3],
                         bl[nt][0], bl[nt][1]);
    }

    const int gid = lane >> 2, tig = lane & 3;
#pragma unroll
    for (int mt = 0; mt < 2; mt++) {
        int grow0 = row0 + wm + mt * 16 + gid;
        int grow1 = grow0 + 8;
        bool v0 = grow0 < M_eff, v1 = grow1 < M_eff;
        int rr0 = v0 ? (use_list ? g_list[grow0] : grow0) : 0;
        int rr1 = v1 ? (use_list ? g_list[grow1] : grow1) : 0;
#pragma unroll
        for (int nt = 0; nt < 4; nt++) {
            int col = n0 + wn + nt * 8 + tig * 2;
            if (v0) *(float2*)&C[(size_t)rr0 * DD + col] = make_float2(acc[mt][nt][0], acc[mt][nt][1]);
            if (v1) *(float2*)&C[(size_t)rr1 * DD + col] = make_float2(acc[mt][nt][2], acc[mt][nt][3]);
        }
    }
}

// ---------------- layer-2: warp per listed node, online softmax ----------------
__global__ void k_layer2(const float* __restrict__ attn2) {
    __shared__ float at_sh[DD];
    for (int i = threadIdx.x; i < DD; i += 256) at_sh[i] = attn2[i];
    __syncthreads();

    int li = (blockIdx.x << 3) + (threadIdx.x >> 5);
    if (li >= g_cnt) return;
    int v = g_list[li];
    int lane = threadIdx.x & 31;
    int jb = lane * 4;

    float4 hd[6], acc[6];
#pragma unroll
    for (int i = 0; i < 6; i++) {
        hd[i] = *(const float4*)&g_hd2[v * DD + i * 128 + jb];
        acc[i] = make_float4(0.f, 0.f, 0.f, 0.f);
    }
    float m = -INFINITY, den = 0.f;

    int st = g_off[v], dg = g_deg[v];
    for (int e = 0; e < dg; e++) {
        int u = g_srcs[st + e];
        const float* hrow = &g_hs2[u * DD];
        float4 hs[6];
        float s = 0.f;
#pragma unroll
        for (int i = 0; i < 6; i++) {
            hs[i] = *(const float4*)&hrow[i * 128 + jb];
            float4 a = *(const float4*)&at_sh[i * 128 + jb];
            s += lrelu(hs[i].x + hd[i].x) * a.x + lrelu(hs[i].y + hd[i].y) * a.y
               + lrelu(hs[i].z + hd[i].z) * a.z + lrelu(hs[i].w + hd[i].w) * a.w;
        }
#pragma unroll
        for (int o = 16; o; o >>= 1) s += __shfl_xor_sync(0xffffffffu, s, o);
        float nm = fmaxf(m, s);
        float c = __expf(m - nm);
        float p = __expf(s - nm);
        den = den * c + p;
#pragma unroll
        for (int i = 0; i < 6; i++) {
            acc[i].x = acc[i].x * c + p * hs[i].x;
            acc[i].y = acc[i].y * c + p * hs[i].y;
            acc[i].z = acc[i].z * c + p * hs[i].z;
            acc[i].w = acc[i].w * c + p * hs[i].w;
        }
        m = nm;
    }
    float inv = 1.f / den;
#pragma unroll
    for (int i = 0; i < 6; i++) {
        float4 o = make_float4(acc[i].x * inv, acc[i].y * inv, acc[i].z * inv, acc[i].w * inv);
        *(float4*)&g_emb[v * DD + i * 128 + jb] = o;
    }
}

// ---------------- final gather + sum ----------------
__global__ void k_out(const int* __restrict__ trj, const int* __restrict__ mins,
                      const int* __restrict__ wkd, const int* __restrict__ day,
                      const int* __restrict__ grd,
                      const float* __restrict__ grid_tab, const float* __restrict__ dayt_tab,
                      const float* __restrict__ wk_tab, const float* __restrict__ day_tab,
                      float* __restrict__ out) {
    int r = blockIdx.x;
    int tok = trj[r], mn = mins[r], wk = wkd[r], dy = day[r], gd = grd[r];
    int s = r & (SS - 1);
    int j = threadIdx.x * 4;
    float4 a = *(const float4*)&g_pe[s * DD + j];
    float4 b = *(const float4*)&g_emb[tok * DD + j];
    float4 c = *(const float4*)&wk_tab[wk * DD + j];
    float4 d = *(const float4*)&dayt_tab[mn * DD + j];
    float4 e = *(const float4*)&day_tab[dy * DD + j];
    float4 f = *(const float4*)&grid_tab[gd * DD + j];
    float4 o;
    o.x = a.x + b.x + c.x + d.x + e.x + f.x;
    o.y = a.y + b.y + c.y + d.y + e.y + f.y;
    o.z = a.z + b.z + c.z + d.z + e.z + f.z;
    o.w = a.w + b.w + c.w + d.w + e.w + f.w;
    *(float4*)&out[r * DD + j] = o;
}

// ---------------- launch ----------------
extern "C" void kernel_launch(void* const* d_in, const int* in_sizes, int n_in,
                              void* d_out, int out_size) {
    const int*   trj      = (const int*)d_in[0];
    const int*   min_list = (const int*)d_in[1];
    const int*   wkd_list = (const int*)d_in[2];
    const int*   day_list = (const int*)d_in[3];
    const int*   grd_list = (const int*)d_in[4];
    const int*   e_src    = (const int*)d_in[6];
    const int*   e_dst    = (const int*)d_in[7];
    const float* feat     = (const float*)d_in[8];
    const float* W_src1   = (const float*)d_in[9];
    const float* W_dst1   = (const float*)d_in[10];
    const float* attn1    = (const float*)d_in[11];
    const float* W_src2   = (const float*)d_in[12];
    const float* W_dst2   = (const float*)d_in[13];
    const float* attn2    = (const float*)d_in[14];
    const float* grid_tab = (const float*)d_in[15];
    const float* dayt_tab = (const float*)d_in[16];
    const float* wk_tab   = (const float*)d_in[17];
    const float* day_tab  = (const float*)d_in[18];
    float* out = (float*)d_out;

    const int smem_bytes = (2 * 128 + 2 * 64) * STRD * 2;   // 104448
    static bool once = false;
    static cudaStream_t s_b;
    static cudaEvent_t ev_root, ev_b;
    if (!once) {
        cudaFuncSetAttribute(k_gemm2_mma, cudaFuncAttributeMaxDynamicSharedMemorySize, smem_bytes);
        cudaStreamCreateWithFlags(&s_b, cudaStreamNonBlocking);
        cudaEventCreateWithFlags(&ev_root, cudaEventDisableTiming);
        cudaEventCreateWithFlags(&ev_b, cudaEventDisableTiming);
        once = true;
    }

    __nv_bfloat16 *wsh, *wsl, *wdh, *wdl;
    cudaGetSymbolAddress((void**)&wsh, g_wsh);
    cudaGetSymbolAddress((void**)&wsl, g_wsl);
    cudaGetSymbolAddress((void**)&wdh, g_wdh);
    cudaGetSymbolAddress((void**)&wdl, g_wdl);
    float *hs2, *hd2;
    cudaGetSymbolAddress((void**)&hs2, g_hs2);
    cudaGetSymbolAddress((void**)&hd2, g_hd2);

    // init, then fork: CSR chain on origin stream, dense prep on s_b
    k_init<<<80, 256>>>();
    cudaEventRecord(ev_root, 0);
    cudaStreamWaitEvent(s_b, ev_root, 0);

    k_hist<<<352, 512>>>(e_dst);
    k_scan<<<1, 1024>>>();
    k_scatter<<<352, 512>>>(e_src, e_dst);

    k_gemm1<<<(NN + 15) / 16, 128, 0, s_b>>>(feat, W_src1, W_dst1);
    k_misc<<<1536 + 384 + 32, 256, 0, s_b>>>(W_src2, W_dst2, trj);
    cudaEventRecord(ev_b, s_b);
    cudaStreamWaitEvent(0, ev_b, 0);

    k_layer1<<<(NN + 7) / 8, 256>>>(attn1);
    dim3 g2(DD / 64, (NN + 127) / 128, 2);
    k_gemm2_mma<<<g2, 256, smem_bytes>>>(wsh, wsl, wdh, wdl, hs2, hd2);
    k_layer2<<<(NN + 7) / 8, 256>>>(attn2);
    k_out<<<BS, 192>>>(trj, min_list, wkd_list, day_list, grd_list,
                       grid_tab, dayt_tab, wk_tab, day_tab, out);
}

// round 6
// speedup vs baseline: 1.8686x; 1.0103x over previous
#include <cuda_runtime.h>
#include <cuda_bf16.h>
#include <math.h>
#include <stdint.h>

#define NN 20000
#define EE 180000
#define DD 768
#define SS 512
#define BS 8192      // B*S
#define HH 128       // HEADS*HID
#define STRD 136     // padded SMEM row stride (bf16 elems)

// ---------------- scratch (device globals; no runtime alloc) ----------------
__device__ float g_hs1[NN * HH];
__device__ float g_hd1[NN * HH];
__device__ __nv_bfloat16 g_h1h[NN * HH];
__device__ __nv_bfloat16 g_h1l[NN * HH];
__device__ __nv_bfloat16 g_wsh[DD * HH];
__device__ __nv_bfloat16 g_wsl[DD * HH];
__device__ __nv_bfloat16 g_wdh[DD * HH];
__device__ __nv_bfloat16 g_wdl[DD * HH];
__device__ float g_hs2[NN * DD];
__device__ float g_hd2[NN * DD];
__device__ float g_emb[NN * DD];
__device__ float g_pe [SS * DD];
__device__ int   g_deg[NN];
__device__ int   g_off[NN];
__device__ int   g_cur[NN];
__device__ int   g_flag[NN];
__device__ int   g_list[NN];
__device__ int   g_srcs[EE];
__device__ int   g_cnt;

__device__ __forceinline__ float lrelu(float x) { return x > 0.f ? x : 0.2f * x; }
__device__ __forceinline__ float elu1(float x)  { return x > 0.f ? x : expm1f(x); }

__device__ __forceinline__ uint32_t smem_u32(const void* p) {
    uint32_t a;
    asm("{ .reg .u64 t; cvta.to.shared.u64 t, %1; cvt.u32.u64 %0, t; }" : "=r"(a) : "l"(p));
    return a;
}

#define LDSM_X4(r0, r1, r2, r3, addr) \
    asm volatile("ldmatrix.sync.aligned.m8n8.x4.shared.b16 {%0,%1,%2,%3}, [%4];" \
                 : "=r"(r0), "=r"(r1), "=r"(r2), "=r"(r3) : "r"(addr))

#define MMA16816(c, a0, a1, a2, a3, b0, b1) \
    asm volatile("mma.sync.aligned.m16n8k16.row.col.f32.bf16.bf16.f32 " \
                 "{%0,%1,%2,%3}, {%4,%5,%6,%7}, {%8,%9}, {%0,%1,%2,%3};" \
                 : "+f"((c)[0]), "+f"((c)[1]), "+f"((c)[2]), "+f"((c)[3]) \
                 : "r"(a0), "r"(a1), "r"(a2), "r"(a3), "r"(b0), "r"(b1))

// ---------------- init ----------------
__global__ void k_init() {
    int i = blockIdx.x * blockDim.x + threadIdx.x;
    int stride = gridDim.x * blockDim.x;
    for (int j = i; j < NN; j += stride) { g_deg[j] = 0; g_cur[j] = 0; g_flag[j] = 0; }
    if (i == 0) g_cnt = 0;
}

// ---------------- CSR build ----------------
__global__ void k_hist(const int* __restrict__ dst) {
    int i = blockIdx.x * blockDim.x + threadIdx.x;
    int stride = gridDim.x * blockDim.x;
    for (int e = i; e < EE; e += stride) atomicAdd(&g_deg[dst[e]], 1);
}

// fast single-block exclusive scan: 1024 threads x 20 serial elements
__global__ void k_scan() {
    __shared__ int wsum[32];
    const int t = threadIdx.x;
    const int PER = (NN + 1023) / 1024;     // 20
    const int base = t * PER;
    int pre[PER];
    int local = 0;
#pragma unroll
    for (int i = 0; i < PER; i++) {
        int idx = base + i;
        int v = (idx < NN) ? g_deg[idx] : 0;
        pre[i] = local;
        local += v;
    }
    const int lane = t & 31, wid = t >> 5;
    int x = local;
#pragma unroll
    for (int o = 1; o < 32; o <<= 1) {
        int y = __shfl_up_sync(0xffffffffu, x, o);
        if (lane >= o) x += y;
    }
    if (lane == 31) wsum[wid] = x;
    __syncthreads();
    if (wid == 0) {
        int s = wsum[lane];
#pragma unroll
        for (int o = 1; o < 32; o <<= 1) {
            int y = __shfl_up_sync(0xffffffffu, s, o);
            if (lane >= o) s += y;
        }
        wsum[lane] = s;
    }
    __syncthreads();
    int texcl = (x - local) + (wid > 0 ? wsum[wid - 1] : 0);
#pragma unroll
    for (int i = 0; i < PER; i++) {
        int idx = base + i;
        if (idx < NN) g_off[idx] = texcl + pre[i];
    }
}

__global__ void k_scatter(const int* __restrict__ src, const int* __restrict__ dst) {
    int i = blockIdx.x * blockDim.x + threadIdx.x;
    int stride = gridDim.x * blockDim.x;
    for (int e = i; e < EE; e += stride) {
        int d = dst[e];
        int pos = g_off[d] + atomicAdd(&g_cur[d], 1);
        g_srcs[pos] = src[e];
    }
}

// ---------------- layer-1 input projections ----------------
__global__ void k_gemm1(const float* __restrict__ feat,
                        const float* __restrict__ Ws, const float* __restrict__ Wd) {
    __shared__ float ws[4 * HH], wd[4 * HH];
    int t = threadIdx.x;                     // 128
    for (int i = t; i < 4 * HH; i += 128) { ws[i] = Ws[i]; wd[i] = Wd[i]; }
    __syncthreads();
    int n0 = blockIdx.x * 16;
    int n1 = min(NN, n0 + 16);
    for (int n = n0; n < n1; n++) {
        float f0 = feat[n * 4 + 0], f1 = feat[n * 4 + 1], f2 = feat[n * 4 + 2], f3 = feat[n * 4 + 3];
        float s = f0 * ws[t] + f1 * ws[HH + t] + f2 * ws[2 * HH + t] + f3 * ws[3 * HH + t];
        float d = f0 * wd[t] + f1 * wd[HH + t] + f2 * wd[2 * HH + t] + f3 * wd[3 * HH + t];
        g_hs1[n * HH + t] = s;
        g_hd1[n * HH + t] = d;
    }
}

// ---------------- layer-1: warp per node, online softmax; emit bf16 hi/lo ----------------
__global__ void k_layer1(const float* __restrict__ attn1) {
    int v = (blockIdx.x << 3) + (threadIdx.x >> 5);
    if (v >= NN) return;
    int lane = threadIdx.x & 31;
    int jb = lane * 4;

    float4 hd = *(const float4*)&g_hd1[v * HH + jb];
    float4 at = *(const float4*)&attn1[jb];
    float4 acc = make_float4(0.f, 0.f, 0.f, 0.f);
    float m = -INFINITY, den = 0.f;

    int st = g_off[v], dg = g_deg[v];
    for (int e = 0; e < dg; e++) {
        int u = g_srcs[st + e];
        float4 hs = *(const float4*)&g_hs1[u * HH + jb];
        float s = lrelu(hs.x + hd.x) * at.x + lrelu(hs.y + hd.y) * at.y
                + lrelu(hs.z + hd.z) * at.z + lrelu(hs.w + hd.w) * at.w;
        s += __shfl_xor_sync(0xffffffffu, s, 1);
        s += __shfl_xor_sync(0xffffffffu, s, 2);
        float nm = fmaxf(m, s);
        float c = __expf(m - nm);
        float p = __expf(s - nm);
        den = den * c + p;
        acc.x = acc.x * c + p * hs.x;
        acc.y = acc.y * c + p * hs.y;
        acc.z = acc.z * c + p * hs.z;
        acc.w = acc.w * c + p * hs.w;
        m = nm;
    }
    float inv = 1.f / den;
    float o[4];
    o[0] = elu1(acc.x * inv); o[1] = elu1(acc.y * inv);
    o[2] = elu1(acc.z * inv); o[3] = elu1(acc.w * inv);
#pragma unroll
    for (int i = 0; i < 4; i++) {
        __nv_bfloat16 h = __float2bfloat16(o[i]);
        g_h1h[v * HH + jb + i] = h;
        g_h1l[v * HH + jb + i] = __float2bfloat16(o[i] - __bfloat162float(h));
    }
}

// ---------------- fused: pe (1536 blocks) + wsplit (384) + flag (32) ----------------
__global__ void k_misc(const float* __restrict__ Ws, const float* __restrict__ Wd,
                       const int* __restrict__ trj) {
    int b = blockIdx.x;
    if (b < 1536) {
        int idx = b * 256 + threadIdx.x;
        int s = idx / DD, d = idx % DD;
        int i2 = d >> 1;
        float div = __expf((float)(2 * i2) * (-9.210340371976184f / (float)DD));
        float ang = (float)s * div;
        g_pe[idx] = (d & 1) ? cosf(ang) : sinf(ang);
    } else if (b < 1536 + 384) {
        int i = (b - 1536) * 256 + threadIdx.x;
        int n = i >> 7, k = i & 127;
        float ws = Ws[k * DD + n];
        __nv_bfloat16 h = __float2bfloat16(ws);
        g_wsh[i] = h;
        g_wsl[i] = __float2bfloat16(ws - __bfloat162float(h));
        float wd = Wd[k * DD + n];
        h = __float2bfloat16(wd);
        g_wdh[i] = h;
        g_wdl[i] = __float2bfloat16(wd - __bfloat162float(h));
    } else {
        int j = (b - 1536 - 384) * 256 + threadIdx.x;
        if (j < BS) {
            int tok = trj[j];
            if (atomicExch(&g_flag[tok], 1) == 0) {
                int p = atomicAdd(&g_cnt, 1);
                g_list[p] = tok;
            }
        }
    }
}

// ---------------- layer-2 GEMM: N-resident. CTA owns 128 rows x all 768 cols. ----------------
// A (hi/lo) loaded to SMEM once; B streamed in 64-col chunks (12 iterations).
// blockIdx.y==0: all NN rows -> hs2 with (Bh0,Bl0); ==1: g_cnt listed rows -> hd2 with (Bh1,Bl1)
__global__ void __launch_bounds__(256, 2) k_gemm2_mma(
        const __nv_bfloat16* __restrict__ Bh0, const __nv_bfloat16* __restrict__ Bl0,
        const __nv_bfloat16* __restrict__ Bh1, const __nv_bfloat16* __restrict__ Bl1,
        float* __restrict__ C0, float* __restrict__ C1) {
    extern __shared__ __nv_bfloat16 sm[];
    __nv_bfloat16* Ah_s = sm;                               // 128 x STRD
    __nv_bfloat16* Al_s = sm + 128 * STRD;                  // 128 x STRD
    __nv_bfloat16* Bh_s = sm + 2 * 128 * STRD;              // 64 x STRD
    __nv_bfloat16* Bl_s = sm + 2 * 128 * STRD + 64 * STRD;  // 64 x STRD

    const int use_list = blockIdx.y;
    const int M_eff = use_list ? g_cnt : NN;
    const int bm = blockIdx.x;
    if (bm * 128 >= M_eff) return;
    const __nv_bfloat16* Bh = use_list ? Bh1 : Bh0;
    const __nv_bfloat16* Bl = use_list ? Bl1 : Bl0;
    float* C = use_list ? C1 : C0;
    const int row0 = bm * 128;
    const int tid = threadIdx.x;

    // load A tile (hi/lo) once
    const uint4 z4 = make_uint4(0, 0, 0, 0);
    for (int i = tid; i < 2048; i += 256) {
        int r = i >> 4, ck = i & 15;
        int so = r * STRD + ck * 8;
        int gr = row0 + r;
        uint4 vh = z4, vl = z4;
        if (gr < M_eff) {
            int rr = use_list ? g_list[gr] : gr;
            vh = *(const uint4*)&g_h1h[rr * HH + ck * 8];
            vl = *(const uint4*)&g_h1l[rr * HH + ck * 8];
        }
        *(uint4*)&Ah_s[so] = vh;
        *(uint4*)&Al_s[so] = vl;
    }

    const int wid = tid >> 5, lane = tid & 31;
    const int wm = (wid >> 1) * 32, wn = (wid & 1) * 32;

    const int a_row = wm + (lane & 15);
    const int a_kof = (lane >> 4) * 8;
    const int q = lane >> 3, rrow = lane & 7;
    const int b_nof = ((q >> 1) ? 8 : 0) + rrow;
    const int b_kof = (q & 1) * 8;

    const uint32_t sAh = smem_u32(Ah_s), sAl = smem_u32(Al_s);
    const uint32_t sBh = smem_u32(Bh_s), sBl = smem_u32(Bl_s);

    // precompute epilogue row mapping
    const int gid = lane >> 2, tig = lane & 3;
    int grow0 = row0 + wm + gid;          // +mt*16, +8 variants below
    bool v00 = (grow0      ) < M_eff, v01 = (grow0 + 8 ) < M_eff;
    bool v10 = (grow0 + 16 ) < M_eff, v11 = (grow0 + 24) < M_eff;
    int rr00 = v00 ? (use_list ? g_list[grow0      ] : grow0      ) : 0;
    int rr01 = v01 ? (use_list ? g_list[grow0 + 8  ] : grow0 + 8  ) : 0;
    int rr10 = v10 ? (use_list ? g_list[grow0 + 16 ] : grow0 + 16 ) : 0;
    int rr11 = v11 ? (use_list ? g_list[grow0 + 24 ] : grow0 + 24 ) : 0;

    for (int bn = 0; bn < DD / 64; bn++) {
        const int n0 = bn * 64;
        // load B chunk
        for (int i = tid; i < 1024; i += 256) {
            int r = i >> 4, ck = i & 15;
            int so = r * STRD + ck * 8;
            int gn = n0 + r;
            *(uint4*)&Bh_s[so] = *(const uint4*)&Bh[gn * HH + ck * 8];
            *(uint4*)&Bl_s[so] = *(const uint4*)&Bl[gn * HH + ck * 8];
        }
        __syncthreads();

        float acc[2][4][4];
#pragma unroll
        for (int mt = 0; mt < 2; mt++)
#pragma unroll
            for (int nt = 0; nt < 4; nt++)
#pragma unroll
                for (int c = 0; c < 4; c++) acc[mt][nt][c] = 0.f;

#pragma unroll
        for (int ks = 0; ks < 8; ks++) {
            const int kbase = ks * 16;
            uint32_t ah[2][4], al[2][4], bh[4][2], bl[4][2];
#pragma unroll
            for (int mt = 0; mt < 2; mt++) {
                uint32_t ad = sAh + ((a_row + mt * 16) * STRD + kbase + a_kof) * 2;
                LDSM_X4(ah[mt][0], ah[mt][1], ah[mt][2], ah[mt][3], ad);
            }
#pragma unroll
            for (int np = 0; np < 2; np++) {
                uint32_t bd = sBh + ((wn + np * 16 + b_nof) * STRD + kbase + b_kof) * 2;
                LDSM_X4(bh[np * 2][0], bh[np * 2][1], bh[np * 2 + 1][0], bh[np * 2 + 1][1], bd);
            }
#pragma unroll
            for (int mt = 0; mt < 2; mt++)
#pragma unroll
                for (int nt = 0; nt < 4; nt++)
                    MMA16816(acc[mt][nt], ah[mt][0], ah[mt][1], ah[mt][2], ah[mt][3],
                             bh[nt][0], bh[nt][1]);
#pragma unroll
            for (int mt = 0; mt < 2; mt++) {
                uint32_t ad = sAl + ((a_row + mt * 16) * STRD + kbase + a_kof) * 2;
                LDSM_X4(al[mt][0], al[mt][1], al[mt][2], al[mt][3], ad);
            }
#pragma unroll
            for (int mt = 0; mt < 2; mt++)
#pragma unroll
                for (int nt = 0; nt < 4; nt++)
                    MMA16816(acc[mt][nt], al[mt][0], al[mt][1], al[mt][2], al[mt][3],
                             bh[nt][0], bh[nt][1]);
#pragma unroll
            for (int np = 0; np < 2; np++) {
                uint32_t bd = sBl + ((wn + np * 16 + b_nof) * STRD + kbase + b_kof) * 2;
                LDSM_X4(bl[np * 2][0], bl[np * 2][1], bl[np * 2 + 1][0], bl[np * 2 + 1][1], bd);
            }
#pragma unroll
            for (int mt = 0; mt < 2; mt++)
#pragma unroll
                for (int nt = 0; nt < 4; nt++)
                    MMA16816(acc[mt][nt], ah[mt][0], ah[mt][1], ah[mt][2], ah[mt][3],
                             bl[nt][0], bl[nt][1]);
        }

        // epilogue for this 64-col chunk
#pragma unroll
        for (int mt = 0; mt < 2; mt++) {
            bool v0 = mt ? v10 : v00, v1 = mt ? v11 : v01;
            int r0 = mt ? rr10 : rr00, r1 = mt ? rr11 : rr01;
#pragma unroll
            for (int nt = 0; nt < 4; nt++) {
                int col = n0 + wn + nt * 8 + tig * 2;
                if (v0) *(float2*)&C[(size_t)r0 * DD + col] = make_float2(acc[mt][nt][0], acc[mt][nt][1]);
                if (v1) *(float2*)&C[(size_t)r1 * DD + col] = make_float2(acc[mt][nt][2], acc[mt][nt][3]);
            }
        }
        __syncthreads();   // protect B smem before next chunk load
    }
}

// ---------------- layer-2: warp per listed node, online softmax ----------------
__global__ void k_layer2(const float* __restrict__ attn2) {
    __shared__ float at_sh[DD];
    for (int i = threadIdx.x; i < DD; i += 256) at_sh[i] = attn2[i];
    __syncthreads();

    int li = (blockIdx.x << 3) + (threadIdx.x >> 5);
    if (li >= g_cnt) return;
    int v = g_list[li];
    int lane = threadIdx.x & 31;
    int jb = lane * 4;

    float4 hd[6], acc[6];
#pragma unroll
    for (int i = 0; i < 6; i++) {
        hd[i] = *(const float4*)&g_hd2[v * DD + i * 128 + jb];
        acc[i] = make_float4(0.f, 0.f, 0.f, 0.f);
    }
    float m = -INFINITY, den = 0.f;

    int st = g_off[v], dg = g_deg[v];
    for (int e = 0; e < dg; e++) {
        int u = g_srcs[st + e];
        const float* hrow = &g_hs2[u * DD];
        float4 hs[6];
        float s = 0.f;
#pragma unroll
        for (int i = 0; i < 6; i++) {
            hs[i] = *(const float4*)&hrow[i * 128 + jb];
            float4 a = *(const float4*)&at_sh[i * 128 + jb];
            s += lrelu(hs[i].x + hd[i].x) * a.x + lrelu(hs[i].y + hd[i].y) * a.y
               + lrelu(hs[i].z + hd[i].z) * a.z + lrelu(hs[i].w + hd[i].w) * a.w;
        }
#pragma unroll
        for (int o = 16; o; o >>= 1) s += __shfl_xor_sync(0xffffffffu, s, o);
        float nm = fmaxf(m, s);
        float c = __expf(m - nm);
        float p = __expf(s - nm);
        den = den * c + p;
#pragma unroll
        for (int i = 0; i < 6; i++) {
            acc[i].x = acc[i].x * c + p * hs[i].x;
            acc[i].y = acc[i].y * c + p * hs[i].y;
            acc[i].z = acc[i].z * c + p * hs[i].z;
            acc[i].w = acc[i].w * c + p * hs[i].w;
        }
        m = nm;
    }
    float inv = 1.f / den;
#pragma unroll
    for (int i = 0; i < 6; i++) {
        float4 o = make_float4(acc[i].x * inv, acc[i].y * inv, acc[i].z * inv, acc[i].w * inv);
        *(float4*)&g_emb[v * DD + i * 128 + jb] = o;
    }
}

// ---------------- final gather + sum ----------------
__global__ void k_out(const int* __restrict__ trj, const int* __restrict__ mins,
                      const int* __restrict__ wkd, const int* __restrict__ day,
                      const int* __restrict__ grd,
                      const float* __restrict__ grid_tab, const float* __restrict__ dayt_tab,
                      const float* __restrict__ wk_tab, const float* __restrict__ day_tab,
                      float* __restrict__ out) {
    int r = blockIdx.x;
    int tok = trj[r], mn = mins[r], wk = wkd[r], dy = day[r], gd = grd[r];
    int s = r & (SS - 1);
    int j = threadIdx.x * 4;
    float4 a = *(const float4*)&g_pe[s * DD + j];
    float4 b = *(const float4*)&g_emb[tok * DD + j];
    float4 c = *(const float4*)&wk_tab[wk * DD + j];
    float4 d = *(const float4*)&dayt_tab[mn * DD + j];
    float4 e = *(const float4*)&day_tab[dy * DD + j];
    float4 f = *(const float4*)&grid_tab[gd * DD + j];
    float4 o;
    o.x = a.x + b.x + c.x + d.x + e.x + f.x;
    o.y = a.y + b.y + c.y + d.y + e.y + f.y;
    o.z = a.z + b.z + c.z + d.z + e.z + f.z;
    o.w = a.w + b.w + c.w + d.w + e.w + f.w;
    *(float4*)&out[r * DD + j] = o;
}

// ---------------- launch ----------------
extern "C" void kernel_launch(void* const* d_in, const int* in_sizes, int n_in,
                              void* d_out, int out_size) {
    const int*   trj      = (const int*)d_in[0];
    const int*   min_list = (const int*)d_in[1];
    const int*   wkd_list = (const int*)d_in[2];
    const int*   day_list = (const int*)d_in[3];
    const int*   grd_list = (const int*)d_in[4];
    const int*   e_src    = (const int*)d_in[6];
    const int*   e_dst    = (const int*)d_in[7];
    const float* feat     = (const float*)d_in[8];
    const float* W_src1   = (const float*)d_in[9];
    const float* W_dst1   = (const float*)d_in[10];
    const float* attn1    = (const float*)d_in[11];
    const float* W_src2   = (const float*)d_in[12];
    const float* W_dst2   = (const float*)d_in[13];
    const float* attn2    = (const float*)d_in[14];
    const float* grid_tab = (const float*)d_in[15];
    const float* dayt_tab = (const float*)d_in[16];
    const float* wk_tab   = (const float*)d_in[17];
    const float* day_tab  = (const float*)d_in[18];
    float* out = (float*)d_out;

    const int smem_bytes = (2 * 128 + 2 * 64) * STRD * 2;   // 104448
    static bool once = false;
    static cudaStream_t s_b;
    static cudaEvent_t ev_root, ev_b;
    if (!once) {
        cudaFuncSetAttribute(k_gemm2_mma, cudaFuncAttributeMaxDynamicSharedMemorySize, smem_bytes);
        cudaStreamCreateWithFlags(&s_b, cudaStreamNonBlocking);
        cudaEventCreateWithFlags(&ev_root, cudaEventDisableTiming);
        cudaEventCreateWithFlags(&ev_b, cudaEventDisableTiming);
        once = true;
    }

    __nv_bfloat16 *wsh, *wsl, *wdh, *wdl;
    cudaGetSymbolAddress((void**)&wsh, g_wsh);
    cudaGetSymbolAddress((void**)&wsl, g_wsl);
    cudaGetSymbolAddress((void**)&wdh, g_wdh);
    cudaGetSymbolAddress((void**)&wdl, g_wdl);
    float *hs2, *hd2;
    cudaGetSymbolAddress((void**)&hs2, g_hs2);
    cudaGetSymbolAddress((void**)&hd2, g_hd2);

    // init, then fork: CSR chain on origin stream, dense prep on s_b
    k_init<<<80, 256>>>();                                   // 0
    cudaEventRecord(ev_root, 0);
    cudaStreamWaitEvent(s_b, ev_root, 0);

    k_hist<<<352, 512>>>(e_dst);                             // 1
    k_scan<<<1, 1024>>>();                                   // 2
    k_gemm1<<<(NN + 15) / 16, 128, 0, s_b>>>(feat, W_src1, W_dst1);  // 3 <- profiled
    k_scatter<<<352, 512>>>(e_src, e_dst);                   // 4
    k_misc<<<1536 + 384 + 32, 256, 0, s_b>>>(W_src2, W_dst2, trj);   // 5
    cudaEventRecord(ev_b, s_b);
    cudaStreamWaitEvent(0, ev_b, 0);

    k_layer1<<<(NN + 7) / 8, 256>>>(attn1);
    dim3 g2((NN + 127) / 128, 2);
    k_gemm2_mma<<<g2, 256, smem_bytes>>>(wsh, wsl, wdh, wdl, hs2, hd2);
    k_layer2<<<(NN + 7) / 8, 256>>>(attn2);
    k_out<<<BS, 192>>>(trj, min_list, wkd_list, day_list, grd_list,
                       grid_tab, dayt_tab, wk_tab, day_tab, out);
}